// round 1
// baseline (speedup 1.0000x reference)
#include <cuda_runtime.h>
#include <math.h>

#define B_    8
#define C_    384
#define N_    1024
#define OUT3  1152     // 3*C
#define NH    12
#define HD    32
#define SCALE 0.17677669529663687f   // 32^-0.5

// Scratch (allocations are forbidden; __device__ globals are the sanctioned path)
static __device__ float g_qkv[B_ * N_ * OUT3];   // (B, N, 1152)  ~37.7 MB
static __device__ float g_att[B_ * N_ * C_];     // (B, N, 384)   ~12.6 MB

// ---------------------------------------------------------------------------
// Kernel 1: qkv[b][m][o] = sum_c x[b][c][m] * Wqkv[o][c]
// Tile 64(m) x 64(o), k-chunk 32, 256 threads, 4x4 micro-tile per thread.
// ---------------------------------------------------------------------------
__global__ __launch_bounds__(256) void qkv_gemm(const float* __restrict__ x,
                                                const float* __restrict__ W) {
    __shared__ float Xs[32][64];   // [k][m]
    __shared__ float Wt[32][68];   // [k][o] transposed, pad 68 (16B-aligned rows)

    const int b  = blockIdx.z;
    const int m0 = blockIdx.y * 64;
    const int n0 = blockIdx.x * 64;
    const int tid = threadIdx.x;
    const int tx = tid & 15, ty = tid >> 4;

    const float* xb = x + (size_t)b * C_ * N_;
    float acc[4][4] = {};

    for (int k0 = 0; k0 < C_; k0 += 32) {
#pragma unroll
        for (int r = 0; r < 2; r++) {
            int f = tid + r * 256;          // 512 float4 total
            int k = f >> 4, m4 = f & 15;
            float4 v = *(const float4*)(xb + (size_t)(k0 + k) * N_ + m0 + m4 * 4);
            *(float4*)&Xs[k][m4 * 4] = v;
        }
#pragma unroll
        for (int r = 0; r < 2; r++) {
            int f = tid + r * 256;
            int o = f >> 3, k4 = f & 7;
            float4 v = *(const float4*)(W + (size_t)(n0 + o) * C_ + k0 + k4 * 4);
            Wt[k4 * 4 + 0][o] = v.x; Wt[k4 * 4 + 1][o] = v.y;
            Wt[k4 * 4 + 2][o] = v.z; Wt[k4 * 4 + 3][o] = v.w;
        }
        __syncthreads();
#pragma unroll
        for (int kk = 0; kk < 32; kk++) {
            float4 a4 = *(const float4*)&Xs[kk][ty * 4];
            float4 b4 = *(const float4*)&Wt[kk][tx * 4];
            float av[4] = {a4.x, a4.y, a4.z, a4.w};
            float bv[4] = {b4.x, b4.y, b4.z, b4.w};
#pragma unroll
            for (int i = 0; i < 4; i++)
#pragma unroll
                for (int j = 0; j < 4; j++) acc[i][j] += av[i] * bv[j];
        }
        __syncthreads();
    }

    float* outp = g_qkv + (size_t)b * N_ * OUT3;
#pragma unroll
    for (int i = 0; i < 4; i++) {
        float4 v = make_float4(acc[i][0], acc[i][1], acc[i][2], acc[i][3]);
        *(float4*)(outp + (size_t)(m0 + ty * 4 + i) * OUT3 + n0 + tx * 4) = v;
    }
}

// ---------------------------------------------------------------------------
// Kernel 2: flash attention. Block = 64 query rows of one (b,h).
// Key tiles of 64; S = Q K^T (4x4/thread), online softmax (16-lane shfl
// row reductions), P staged in smem, PV register-tiled (4 rows x 2 dims).
// ---------------------------------------------------------------------------
__global__ __launch_bounds__(256) void attn_kernel() {
    const int bh = blockIdx.y;
    const int b = bh / NH, h = bh % NH;
    const int i0 = blockIdx.x * 64;

    const float* base = g_qkv + (size_t)b * N_ * OUT3 + h * HD;

    __shared__ float Qt[32][68];   // [d][i]
    __shared__ float Kt[32][68];   // [d][j]
    __shared__ float Vs[64][36];   // [j][d]
    __shared__ float Pt[64][68];   // [i][j]

    const int tid = threadIdx.x;
    const int tx = tid & 15, ty = tid >> 4;

    // Load Q transposed (once)
#pragma unroll
    for (int r = 0; r < 2; r++) {
        int f = tid + r * 256;
        int i = f >> 3, d4 = f & 7;
        float4 q = *(const float4*)(base + (size_t)(i0 + i) * OUT3 + d4 * 4);
        Qt[d4 * 4 + 0][i] = q.x; Qt[d4 * 4 + 1][i] = q.y;
        Qt[d4 * 4 + 2][i] = q.z; Qt[d4 * 4 + 3][i] = q.w;
    }

    float m_run[4], l_run[4], O[4][2];
#pragma unroll
    for (int i = 0; i < 4; i++) {
        m_run[i] = -1e30f; l_run[i] = 0.f; O[i][0] = 0.f; O[i][1] = 0.f;
    }

    for (int kt = 0; kt < 16; kt++) {
        const int j0 = kt * 64;
        __syncthreads();   // previous iteration's PV readers done
#pragma unroll
        for (int r = 0; r < 2; r++) {
            int f = tid + r * 256;
            int j = f >> 3, d4 = f & 7;
            const float* rk = base + 384 + (size_t)(j0 + j) * OUT3 + d4 * 4;
            float4 kv = *(const float4*)rk;
            Kt[d4 * 4 + 0][j] = kv.x; Kt[d4 * 4 + 1][j] = kv.y;
            Kt[d4 * 4 + 2][j] = kv.z; Kt[d4 * 4 + 3][j] = kv.w;
            float4 vv = *(const float4*)(rk + 384);
            *(float4*)&Vs[j][d4 * 4] = vv;
        }
        __syncthreads();

        // S = Q K^T  (rows i = ty*4.., cols j = tx*4..)
        float s[4][4] = {};
#pragma unroll
        for (int d = 0; d < 32; d++) {
            float4 a4 = *(const float4*)&Qt[d][ty * 4];
            float4 b4 = *(const float4*)&Kt[d][tx * 4];
            float av[4] = {a4.x, a4.y, a4.z, a4.w};
            float bv[4] = {b4.x, b4.y, b4.z, b4.w};
#pragma unroll
            for (int i = 0; i < 4; i++)
#pragma unroll
                for (int j = 0; j < 4; j++) s[i][j] += av[i] * bv[j];
        }

        // Online softmax per row; stage P in smem
#pragma unroll
        for (int i = 0; i < 4; i++) {
            float tm = -1e30f;
#pragma unroll
            for (int j = 0; j < 4; j++) { s[i][j] *= SCALE; tm = fmaxf(tm, s[i][j]); }
#pragma unroll
            for (int w = 8; w >= 1; w >>= 1)
                tm = fmaxf(tm, __shfl_xor_sync(0xffffffffu, tm, w));
            float mn = fmaxf(m_run[i], tm);
            float corr = __expf(m_run[i] - mn);
            float p[4], rs = 0.f;
#pragma unroll
            for (int j = 0; j < 4; j++) { p[j] = __expf(s[i][j] - mn); rs += p[j]; }
#pragma unroll
            for (int w = 8; w >= 1; w >>= 1)
                rs += __shfl_xor_sync(0xffffffffu, rs, w);
            l_run[i] = l_run[i] * corr + rs;
            m_run[i] = mn;
            O[i][0] *= corr; O[i][1] *= corr;
            *(float4*)&Pt[ty * 4 + i][tx * 4] = make_float4(p[0], p[1], p[2], p[3]);
        }
        __syncthreads();

        // O += P V   (cols d = tx*2, tx*2+1)
#pragma unroll
        for (int j4 = 0; j4 < 64; j4 += 4) {
            float4 pa[4];
#pragma unroll
            for (int i = 0; i < 4; i++) pa[i] = *(const float4*)&Pt[ty * 4 + i][j4];
#pragma unroll
            for (int jj = 0; jj < 4; jj++) {
                float2 v = *(const float2*)&Vs[j4 + jj][tx * 2];
#pragma unroll
                for (int i = 0; i < 4; i++) {
                    float pv = (&pa[i].x)[jj];
                    O[i][0] += pv * v.x; O[i][1] += pv * v.y;
                }
            }
        }
    }

    // Epilogue: normalize and write att (B, N, C) with c = h*32 + d
    float* ap = g_att + ((size_t)b * N_ + i0) * C_ + h * HD;
#pragma unroll
    for (int i = 0; i < 4; i++) {
        float inv = 1.0f / l_run[i];
        float2 o2 = make_float2(O[i][0] * inv, O[i][1] * inv);
        *(float2*)(ap + (size_t)(ty * 4 + i) * C_ + tx * 2) = o2;
    }
}

// ---------------------------------------------------------------------------
// Kernel 3: out[b][o][m] = sum_c att[b][m][c] * Wp[o][c] + bp[o]
// Tile 64(o) x 64(m); output written transposed == final (B,C,H,W) layout.
// ---------------------------------------------------------------------------
__global__ __launch_bounds__(256) void proj_gemm(const float* __restrict__ Wp,
                                                 const float* __restrict__ bp,
                                                 float* __restrict__ out) {
    __shared__ float At[32][68];   // [c][m]
    __shared__ float Wt[32][68];   // [c][o]

    const int b  = blockIdx.z;
    const int m0 = blockIdx.x * 64;
    const int o0 = blockIdx.y * 64;
    const int tid = threadIdx.x;
    const int tx = tid & 15, ty = tid >> 4;

    const float* ab = g_att + (size_t)b * N_ * C_;
    float acc[4][4] = {};   // [o-frag][m-frag]

    for (int k0 = 0; k0 < C_; k0 += 32) {
#pragma unroll
        for (int r = 0; r < 2; r++) {
            int f = tid + r * 256;
            int m = f >> 3, k4 = f & 7;
            float4 a = *(const float4*)(ab + (size_t)(m0 + m) * C_ + k0 + k4 * 4);
            At[k4 * 4 + 0][m] = a.x; At[k4 * 4 + 1][m] = a.y;
            At[k4 * 4 + 2][m] = a.z; At[k4 * 4 + 3][m] = a.w;
        }
#pragma unroll
        for (int r = 0; r < 2; r++) {
            int f = tid + r * 256;
            int o = f >> 3, k4 = f & 7;
            float4 w = *(const float4*)(Wp + (size_t)(o0 + o) * C_ + k0 + k4 * 4);
            Wt[k4 * 4 + 0][o] = w.x; Wt[k4 * 4 + 1][o] = w.y;
            Wt[k4 * 4 + 2][o] = w.z; Wt[k4 * 4 + 3][o] = w.w;
        }
        __syncthreads();
#pragma unroll
        for (int kk = 0; kk < 32; kk++) {
            float4 a4 = *(const float4*)&At[kk][tx * 4];   // m frag
            float4 b4 = *(const float4*)&Wt[kk][ty * 4];   // o frag
            float av[4] = {a4.x, a4.y, a4.z, a4.w};
            float bv[4] = {b4.x, b4.y, b4.z, b4.w};
#pragma unroll
            for (int i = 0; i < 4; i++)
#pragma unroll
                for (int j = 0; j < 4; j++) acc[i][j] += bv[i] * av[j];
        }
        __syncthreads();
    }

    float* ob = out + (size_t)b * C_ * N_;
#pragma unroll
    for (int i = 0; i < 4; i++) {
        int o = o0 + ty * 4 + i;
        float bias = bp[o];
        float4 v = make_float4(acc[i][0] + bias, acc[i][1] + bias,
                               acc[i][2] + bias, acc[i][3] + bias);
        *(float4*)(ob + (size_t)o * N_ + m0 + tx * 4) = v;
    }
}

// ---------------------------------------------------------------------------
extern "C" void kernel_launch(void* const* d_in, const int* in_sizes, int n_in,
                              void* d_out, int out_size) {
    const float* x     = (const float*)d_in[0];   // (8,384,32,32)
    const float* W_qkv = (const float*)d_in[1];   // (1152,384)
    const float* W_prj = (const float*)d_in[2];   // (384,384)
    const float* b_prj = (const float*)d_in[3];   // (384,)
    float* out = (float*)d_out;

    (void)in_sizes; (void)n_in; (void)out_size;

    dim3 g1(OUT3 / 64, N_ / 64, B_);     // 18 x 16 x 8
    qkv_gemm<<<g1, 256>>>(x, W_qkv);

    dim3 g2(N_ / 64, B_ * NH);           // 16 x 96
    attn_kernel<<<g2, 256>>>();

    dim3 g3(N_ / 64, C_ / 64, B_);       // 16 x 6 x 8
    proj_gemm<<<g3, 256>>>(W_prj, b_prj, out);
}

// round 2
// speedup vs baseline: 1.9790x; 1.9790x over previous
#include <cuda_runtime.h>
#include <cuda_bf16.h>
#include <math.h>

#define B_    8
#define NH    12
#define N_    1024
#define C_    384
#define CP    192       // C/2 (bf16x2 pairs per row)
#define O3    1152
#define O3P   576       // O3/2
#define SCALE 0.17677669529663687f

// ---------------- scratch (bf16x2 packed as u32) ----------------
static __device__ unsigned g_xT_hi[B_ * N_ * CP];
static __device__ unsigned g_xT_lo[B_ * N_ * CP];
static __device__ unsigned g_wq_hi[O3 * CP];
static __device__ unsigned g_wq_lo[O3 * CP];
static __device__ unsigned g_wp_hi[C_ * CP];
static __device__ unsigned g_wp_lo[C_ * CP];
static __device__ unsigned g_qkv_hi[B_ * N_ * O3P];
static __device__ unsigned g_qkv_lo[B_ * N_ * O3P];
static __device__ unsigned g_att_hi[B_ * N_ * CP];
static __device__ unsigned g_att_lo[B_ * N_ * CP];

// split two floats into packed bf16x2 hi + lo (lo = residual)
__device__ __forceinline__ void split2(float f0, float f1, unsigned& hi, unsigned& lo) {
    unsigned h, l;
    asm("cvt.rn.bf16x2.f32 %0, %1, %2;" : "=r"(h) : "f"(f1), "f"(f0));
    float h0 = __uint_as_float(h << 16);
    float h1 = __uint_as_float(h & 0xffff0000u);
    float r0 = f0 - h0, r1 = f1 - h1;
    asm("cvt.rn.bf16x2.f32 %0, %1, %2;" : "=r"(l) : "f"(r1), "f"(r0));
    hi = h; lo = l;
}

__device__ __forceinline__ void mma16816(float* d, const unsigned* a, const unsigned* b) {
    asm volatile(
        "mma.sync.aligned.m16n8k16.row.col.f32.bf16.bf16.f32 "
        "{%0,%1,%2,%3}, {%4,%5,%6,%7}, {%8,%9}, {%0,%1,%2,%3};"
        : "+f"(d[0]), "+f"(d[1]), "+f"(d[2]), "+f"(d[3])
        : "r"(a[0]), "r"(a[1]), "r"(a[2]), "r"(a[3]), "r"(b[0]), "r"(b[1]));
}

// ---------------- pre-kernel 1: transpose + split x -> xT (bf16 hi/lo) ------
__global__ __launch_bounds__(256) void split_x(const float* __restrict__ x) {
    __shared__ float t[32][33];
    const int k0 = blockIdx.x * 32, m0 = blockIdx.y * 32, b = blockIdx.z;
    const int tx = threadIdx.x & 31, ty = threadIdx.x >> 5;
    const float* xb = x + ((size_t)b * C_ + k0) * N_ + m0;
#pragma unroll
    for (int q = 0; q < 4; q++) t[ty + q * 8][tx] = xb[(size_t)(ty + q * 8) * N_ + tx];
    __syncthreads();
    for (int it = threadIdx.x; it < 512; it += 256) {
        int mp = it >> 4, kp = it & 15;
        unsigned hi, lo;
        split2(t[kp * 2][mp], t[kp * 2 + 1][mp], hi, lo);
        size_t idx = ((size_t)b * N_ + m0 + mp) * CP + (k0 >> 1) + kp;
        g_xT_hi[idx] = hi; g_xT_lo[idx] = lo;
    }
}

// ---------------- pre-kernel 2: split weights ----------------
__global__ __launch_bounds__(256) void split_w(const float* __restrict__ wq,
                                               const float* __restrict__ wp) {
    const int NQ = O3 * CP, NP = C_ * CP;
    int i = blockIdx.x * 256 + threadIdx.x;
    if (i < NQ) {
        float2 f = *(const float2*)(wq + 2 * (size_t)i);
        unsigned hi, lo; split2(f.x, f.y, hi, lo);
        g_wq_hi[i] = hi; g_wq_lo[i] = lo;
    } else if (i < NQ + NP) {
        int j = i - NQ;
        float2 f = *(const float2*)(wp + 2 * (size_t)j);
        unsigned hi, lo; split2(f.x, f.y, hi, lo);
        g_wp_hi[j] = hi; g_wp_lo[j] = lo;
    }
}

// ---------------- GEMM: C[m][n] = sum_k A[m][k]*B[n][k], bf16-split mma ----
// Block 128m x 64n, 256 threads (8 warps, 4m x 2n). K-chunk 32.
// EPI=0: A=xT, B=wq, write g_qkv hi/lo.   EPI=1: A=att, B=wp, fp32 out+bias.
template <int EPI>
__global__ __launch_bounds__(256) void gemm_bf16(const float* __restrict__ bias,
                                                 float* __restrict__ out) {
    __shared__ unsigned As_h[128 * 20], As_l[128 * 20];
    __shared__ unsigned Bs_h[64 * 20],  Bs_l[64 * 20];

    const unsigned* Ah = EPI ? g_att_hi : g_xT_hi;
    const unsigned* Al = EPI ? g_att_lo : g_xT_lo;
    const unsigned* Bh = EPI ? g_wp_hi  : g_wq_hi;
    const unsigned* Bl = EPI ? g_wp_lo  : g_wq_lo;

    const int b = blockIdx.z;
    const int m0 = blockIdx.y * 128, n0 = blockIdx.x * 64;
    const int tid = threadIdx.x, lane = tid & 31, wid = tid >> 5;
    const int wm = (wid >> 1) * 32, wn = (wid & 1) * 32;
    const int r = lane >> 2, c = lane & 3;

    float acc[2][4][4] = {};

    const int arow = tid >> 1, ahalf = tid & 1;
    const int brow = tid >> 2, bq = tid & 3;
    const unsigned* agp = Ah + ((size_t)(b * N_ + m0 + arow)) * CP + ahalf * 8;
    const unsigned* agl = Al + ((size_t)(b * N_ + m0 + arow)) * CP + ahalf * 8;
    const unsigned* bgp = Bh + (size_t)(n0 + brow) * CP + bq * 4;
    const unsigned* bgl = Bl + (size_t)(n0 + brow) * CP + bq * 4;

    for (int kc = 0; kc < 12; kc++) {
        __syncthreads();
        {
            uint4 v0 = *(const uint4*)(agp + kc * 16);
            uint4 v1 = *(const uint4*)(agp + kc * 16 + 4);
            *(uint4*)&As_h[arow * 20 + ahalf * 8]     = v0;
            *(uint4*)&As_h[arow * 20 + ahalf * 8 + 4] = v1;
            uint4 u0 = *(const uint4*)(agl + kc * 16);
            uint4 u1 = *(const uint4*)(agl + kc * 16 + 4);
            *(uint4*)&As_l[arow * 20 + ahalf * 8]     = u0;
            *(uint4*)&As_l[arow * 20 + ahalf * 8 + 4] = u1;
            uint4 w0 = *(const uint4*)(bgp + kc * 16);
            *(uint4*)&Bs_h[brow * 20 + bq * 4] = w0;
            uint4 w1 = *(const uint4*)(bgl + kc * 16);
            *(uint4*)&Bs_l[brow * 20 + bq * 4] = w1;
        }
        __syncthreads();

#pragma unroll
        for (int ks = 0; ks < 2; ks++) {
            unsigned ah[2][4], al[2][4];
#pragma unroll
            for (int mt = 0; mt < 2; mt++) {
                int base = wm + mt * 16;
                ah[mt][0] = As_h[(base + r) * 20 + ks * 8 + c];
                ah[mt][1] = As_h[(base + r + 8) * 20 + ks * 8 + c];
                ah[mt][2] = As_h[(base + r) * 20 + ks * 8 + 4 + c];
                ah[mt][3] = As_h[(base + r + 8) * 20 + ks * 8 + 4 + c];
                al[mt][0] = As_l[(base + r) * 20 + ks * 8 + c];
                al[mt][1] = As_l[(base + r + 8) * 20 + ks * 8 + c];
                al[mt][2] = As_l[(base + r) * 20 + ks * 8 + 4 + c];
                al[mt][3] = As_l[(base + r + 8) * 20 + ks * 8 + 4 + c];
            }
#pragma unroll
            for (int nt = 0; nt < 4; nt++) {
                unsigned bhf[2], blf[2];
                bhf[0] = Bs_h[(wn + nt * 8 + r) * 20 + ks * 8 + c];
                bhf[1] = Bs_h[(wn + nt * 8 + r) * 20 + ks * 8 + 4 + c];
                blf[0] = Bs_l[(wn + nt * 8 + r) * 20 + ks * 8 + c];
                blf[1] = Bs_l[(wn + nt * 8 + r) * 20 + ks * 8 + 4 + c];
#pragma unroll
                for (int mt = 0; mt < 2; mt++) {
                    mma16816(acc[mt][nt], ah[mt], bhf);
                    mma16816(acc[mt][nt], al[mt], bhf);
                    mma16816(acc[mt][nt], ah[mt], blf);
                }
            }
        }
    }

    if (EPI == 0) {
#pragma unroll
        for (int mt = 0; mt < 2; mt++)
#pragma unroll
            for (int nt = 0; nt < 4; nt++) {
                int m = m0 + wm + mt * 16 + r;
                int colp = (n0 >> 1) + (wn >> 1) + nt * 4 + c;
                unsigned hi, lo;
                split2(acc[mt][nt][0], acc[mt][nt][1], hi, lo);
                g_qkv_hi[(size_t)(b * N_ + m) * O3P + colp] = hi;
                g_qkv_lo[(size_t)(b * N_ + m) * O3P + colp] = lo;
                split2(acc[mt][nt][2], acc[mt][nt][3], hi, lo);
                g_qkv_hi[(size_t)(b * N_ + m + 8) * O3P + colp] = hi;
                g_qkv_lo[(size_t)(b * N_ + m + 8) * O3P + colp] = lo;
            }
    } else {
#pragma unroll
        for (int mt = 0; mt < 2; mt++)
#pragma unroll
            for (int nt = 0; nt < 4; nt++)
#pragma unroll
                for (int q = 0; q < 4; q++) {
                    int o = n0 + wn + nt * 8 + 2 * c + (q & 1);
                    int m = m0 + wm + mt * 16 + r + ((q >> 1) * 8);
                    out[((size_t)b * C_ + o) * N_ + m] = acc[mt][nt][q] + bias[o];
                }
    }
}

// ---------------- flash attention, bf16-split mma ----------------
// Block = 64 queries of one (b,h), 128 threads (4 warps x 16 rows).
__global__ __launch_bounds__(128) void attn_bf16() {
    __shared__ unsigned Ks_h[64 * 20], Ks_l[64 * 20];
    __shared__ unsigned Vs_h[32 * 36], Vs_l[32 * 36];

    const int tid = threadIdx.x, lane = tid & 31, wid = tid >> 5;
    const int bh = blockIdx.y, b = bh / NH, h = bh % NH;
    const int i0 = blockIdx.x * 64;
    const int iw = i0 + wid * 16;
    const int r = lane >> 2, c = lane & 3;

    // Q fragments, loaded once from global
    unsigned qh[2][4], ql[2][4];
    {
        const unsigned* qb_h = g_qkv_hi + (size_t)(b * N_ + iw) * O3P + h * 16;
        const unsigned* qb_l = g_qkv_lo + (size_t)(b * N_ + iw) * O3P + h * 16;
#pragma unroll
        for (int ks = 0; ks < 2; ks++) {
            qh[ks][0] = qb_h[(size_t)r * O3P + ks * 8 + c];
            qh[ks][1] = qb_h[(size_t)(r + 8) * O3P + ks * 8 + c];
            qh[ks][2] = qb_h[(size_t)r * O3P + ks * 8 + 4 + c];
            qh[ks][3] = qb_h[(size_t)(r + 8) * O3P + ks * 8 + 4 + c];
            ql[ks][0] = qb_l[(size_t)r * O3P + ks * 8 + c];
            ql[ks][1] = qb_l[(size_t)(r + 8) * O3P + ks * 8 + c];
            ql[ks][2] = qb_l[(size_t)r * O3P + ks * 8 + 4 + c];
            ql[ks][3] = qb_l[(size_t)(r + 8) * O3P + ks * 8 + 4 + c];
        }
    }

    float m_run[2] = {-1e30f, -1e30f}, l_run[2] = {0.f, 0.f};
    float acc_o[4][4] = {};

    for (int jt = 0; jt < 16; jt++) {
        __syncthreads();
        {   // stage K tile [j=64][dpair=16] hi/lo
            int row = tid >> 1, half = tid & 1;
            const unsigned* sh = g_qkv_hi + (size_t)(b * N_ + jt * 64 + row) * O3P + 192 + h * 16 + half * 8;
            const unsigned* sl = g_qkv_lo + (size_t)(b * N_ + jt * 64 + row) * O3P + 192 + h * 16 + half * 8;
            uint4 v0 = *(const uint4*)sh, v1 = *(const uint4*)(sh + 4);
            *(uint4*)&Ks_h[row * 20 + half * 8]     = v0;
            *(uint4*)&Ks_h[row * 20 + half * 8 + 4] = v1;
            uint4 u0 = *(const uint4*)sl, u1 = *(const uint4*)(sl + 4);
            *(uint4*)&Ks_l[row * 20 + half * 8]     = u0;
            *(uint4*)&Ks_l[row * 20 + half * 8 + 4] = u1;
        }
        {   // stage V tile transposed -> [d=32][jpair=32] hi/lo
            int jp = tid & 31, dg = tid >> 5;  // dg 0..3 (8 d each)
            const unsigned* sh = g_qkv_hi + (size_t)(b * N_ + jt * 64 + jp * 2) * O3P + 384 + h * 16 + dg * 4;
            const unsigned* sl = g_qkv_lo + (size_t)(b * N_ + jt * 64 + jp * 2) * O3P + 384 + h * 16 + dg * 4;
            uint4 va = *(const uint4*)sh, vb = *(const uint4*)(sh + O3P);
            unsigned aw[4] = {va.x, va.y, va.z, va.w};
            unsigned bw[4] = {vb.x, vb.y, vb.z, vb.w};
#pragma unroll
            for (int e = 0; e < 8; e++)
                Vs_h[(dg * 8 + e) * 36 + jp] =
                    __byte_perm(aw[e >> 1], bw[e >> 1], (e & 1) ? 0x7632 : 0x5410);
            uint4 ua = *(const uint4*)sl, ub = *(const uint4*)(sl + O3P);
            unsigned cw[4] = {ua.x, ua.y, ua.z, ua.w};
            unsigned dw[4] = {ub.x, ub.y, ub.z, ub.w};
#pragma unroll
            for (int e = 0; e < 8; e++)
                Vs_l[(dg * 8 + e) * 36 + jp] =
                    __byte_perm(cw[e >> 1], dw[e >> 1], (e & 1) ? 0x7632 : 0x5410);
        }
        __syncthreads();

        // S = Q K^T
        float s[8][4] = {};
#pragma unroll
        for (int ks = 0; ks < 2; ks++)
#pragma unroll
            for (int nt = 0; nt < 8; nt++) {
                unsigned kb[2], kl[2];
                kb[0] = Ks_h[(nt * 8 + r) * 20 + ks * 8 + c];
                kb[1] = Ks_h[(nt * 8 + r) * 20 + ks * 8 + 4 + c];
                kl[0] = Ks_l[(nt * 8 + r) * 20 + ks * 8 + c];
                kl[1] = Ks_l[(nt * 8 + r) * 20 + ks * 8 + 4 + c];
                mma16816(s[nt], qh[ks], kb);
                mma16816(s[nt], ql[ks], kb);
                mma16816(s[nt], qh[ks], kl);
            }

        // online softmax (rows r and r+8; each row shared by 4 lanes)
        float mx0 = m_run[0], mx1 = m_run[1];
#pragma unroll
        for (int nt = 0; nt < 8; nt++) {
            s[nt][0] *= SCALE; s[nt][1] *= SCALE; s[nt][2] *= SCALE; s[nt][3] *= SCALE;
            mx0 = fmaxf(mx0, fmaxf(s[nt][0], s[nt][1]));
            mx1 = fmaxf(mx1, fmaxf(s[nt][2], s[nt][3]));
        }
        mx0 = fmaxf(mx0, __shfl_xor_sync(0xffffffffu, mx0, 1));
        mx0 = fmaxf(mx0, __shfl_xor_sync(0xffffffffu, mx0, 2));
        mx1 = fmaxf(mx1, __shfl_xor_sync(0xffffffffu, mx1, 1));
        mx1 = fmaxf(mx1, __shfl_xor_sync(0xffffffffu, mx1, 2));
        float corr0 = __expf(m_run[0] - mx0);
        float corr1 = __expf(m_run[1] - mx1);
        float rs0 = 0.f, rs1 = 0.f;
#pragma unroll
        for (int nt = 0; nt < 8; nt++) {
            s[nt][0] = __expf(s[nt][0] - mx0);
            s[nt][1] = __expf(s[nt][1] - mx0);
            s[nt][2] = __expf(s[nt][2] - mx1);
            s[nt][3] = __expf(s[nt][3] - mx1);
            rs0 += s[nt][0] + s[nt][1];
            rs1 += s[nt][2] + s[nt][3];
        }
        rs0 += __shfl_xor_sync(0xffffffffu, rs0, 1);
        rs0 += __shfl_xor_sync(0xffffffffu, rs0, 2);
        rs1 += __shfl_xor_sync(0xffffffffu, rs1, 1);
        rs1 += __shfl_xor_sync(0xffffffffu, rs1, 2);
        l_run[0] = l_run[0] * corr0 + rs0;
        l_run[1] = l_run[1] * corr1 + rs1;
        m_run[0] = mx0; m_run[1] = mx1;
#pragma unroll
        for (int nt = 0; nt < 4; nt++) {
            acc_o[nt][0] *= corr0; acc_o[nt][1] *= corr0;
            acc_o[nt][2] *= corr1; acc_o[nt][3] *= corr1;
        }

        // O += P V  (P fragments built in-register from S accumulators)
#pragma unroll
        for (int kk = 0; kk < 4; kk++) {
            unsigned ph[4], pl[4];
            split2(s[2 * kk][0],     s[2 * kk][1],     ph[0], pl[0]);
            split2(s[2 * kk][2],     s[2 * kk][3],     ph[1], pl[1]);
            split2(s[2 * kk + 1][0], s[2 * kk + 1][1], ph[2], pl[2]);
            split2(s[2 * kk + 1][2], s[2 * kk + 1][3], ph[3], pl[3]);
#pragma unroll
            for (int nt = 0; nt < 4; nt++) {
                unsigned vh[2], vl[2];
                vh[0] = Vs_h[(nt * 8 + r) * 36 + kk * 8 + c];
                vh[1] = Vs_h[(nt * 8 + r) * 36 + kk * 8 + 4 + c];
                vl[0] = Vs_l[(nt * 8 + r) * 36 + kk * 8 + c];
                vl[1] = Vs_l[(nt * 8 + r) * 36 + kk * 8 + 4 + c];
                mma16816(acc_o[nt], ph, vh);
                mma16816(acc_o[nt], pl, vh);
                mma16816(acc_o[nt], ph, vl);
            }
        }
    }

    // epilogue: normalize, split to bf16 hi/lo, store att
    float inv0 = 1.0f / l_run[0], inv1 = 1.0f / l_run[1];
#pragma unroll
    for (int nt = 0; nt < 4; nt++) {
        unsigned hi, lo;
        split2(acc_o[nt][0] * inv0, acc_o[nt][1] * inv0, hi, lo);
        size_t idx0 = (size_t)(b * N_ + iw + r) * CP + h * 16 + nt * 4 + c;
        g_att_hi[idx0] = hi; g_att_lo[idx0] = lo;
        split2(acc_o[nt][2] * inv1, acc_o[nt][3] * inv1, hi, lo);
        size_t idx1 = (size_t)(b * N_ + iw + r + 8) * CP + h * 16 + nt * 4 + c;
        g_att_hi[idx1] = hi; g_att_lo[idx1] = lo;
    }
}

// ---------------------------------------------------------------------------
extern "C" void kernel_launch(void* const* d_in, const int* in_sizes, int n_in,
                              void* d_out, int out_size) {
    const float* x     = (const float*)d_in[0];
    const float* W_qkv = (const float*)d_in[1];
    const float* W_prj = (const float*)d_in[2];
    const float* b_prj = (const float*)d_in[3];
    float* out = (float*)d_out;
    (void)in_sizes; (void)n_in; (void)out_size;

    dim3 gt(C_ / 32, N_ / 32, B_);           // 12 x 32 x 8
    split_x<<<gt, 256>>>(x);

    split_w<<<(O3 * CP + C_ * CP + 255) / 256, 256>>>(W_qkv, W_prj);

    dim3 g1(O3 / 64, N_ / 128, B_);          // 18 x 8 x 8
    gemm_bf16<0><<<g1, 256>>>(nullptr, nullptr);

    dim3 g2(N_ / 64, B_ * NH);               // 16 x 96
    attn_bf16<<<g2, 128>>>();

    dim3 g3(C_ / 64, N_ / 128, B_);          // 6 x 8 x 8
    gemm_bf16<1><<<g3, 256>>>(b_prj, out);
}

// round 3
// speedup vs baseline: 2.2679x; 1.1460x over previous
#include <cuda_runtime.h>
#include <cuda_bf16.h>
#include <math.h>

#define B_    8
#define NH    12
#define N_    1024
#define C_    384
#define CP    192       // C/2 (bf16x2 pairs per row)
#define O3    1152
#define O3P   576       // O3/2
#define SCALE 0.17677669529663687f

// ---------------- scratch (bf16x2 packed as u32) ----------------
static __device__ unsigned g_xT_hi[B_ * N_ * CP];
static __device__ unsigned g_xT_lo[B_ * N_ * CP];
static __device__ unsigned g_wq_hi[O3 * CP];
static __device__ unsigned g_wq_lo[O3 * CP];
static __device__ unsigned g_wp_hi[C_ * CP];
static __device__ unsigned g_wp_lo[C_ * CP];
static __device__ unsigned g_qkv_hi[B_ * N_ * O3P];
static __device__ unsigned g_qkv_lo[B_ * N_ * O3P];
static __device__ unsigned g_att_hi[B_ * N_ * CP];
static __device__ unsigned g_att_lo[B_ * N_ * CP];

// split two floats into packed bf16x2 hi + lo (lo = residual)
__device__ __forceinline__ void split2(float f0, float f1, unsigned& hi, unsigned& lo) {
    unsigned h, l;
    asm("cvt.rn.bf16x2.f32 %0, %1, %2;" : "=r"(h) : "f"(f1), "f"(f0));
    float h0 = __uint_as_float(h << 16);
    float h1 = __uint_as_float(h & 0xffff0000u);
    float r0 = f0 - h0, r1 = f1 - h1;
    asm("cvt.rn.bf16x2.f32 %0, %1, %2;" : "=r"(l) : "f"(r1), "f"(r0));
    hi = h; lo = l;
}

__device__ __forceinline__ void mma16816(float* d, const unsigned* a, const unsigned* b) {
    asm volatile(
        "mma.sync.aligned.m16n8k16.row.col.f32.bf16.bf16.f32 "
        "{%0,%1,%2,%3}, {%4,%5,%6,%7}, {%8,%9}, {%0,%1,%2,%3};"
        : "+f"(d[0]), "+f"(d[1]), "+f"(d[2]), "+f"(d[3])
        : "r"(a[0]), "r"(a[1]), "r"(a[2]), "r"(a[3]), "r"(b[0]), "r"(b[1]));
}

__device__ __forceinline__ unsigned smem_u32p(const void* p) {
    return (unsigned)__cvta_generic_to_shared(p);
}

__device__ __forceinline__ void ldsm_x4(unsigned& r0, unsigned& r1,
                                        unsigned& r2, unsigned& r3, unsigned addr) {
    asm volatile("ldmatrix.sync.aligned.m8n8.x4.shared.b16 {%0,%1,%2,%3}, [%4];"
                 : "=r"(r0), "=r"(r1), "=r"(r2), "=r"(r3) : "r"(addr));
}

// ---------------- pre-kernel 1: transpose + split x -> xT ----------------
__global__ __launch_bounds__(256) void split_x(const float* __restrict__ x) {
    __shared__ float t[32][33];
    const int k0 = blockIdx.x * 32, m0 = blockIdx.y * 32, b = blockIdx.z;
    const int tx = threadIdx.x & 31, ty = threadIdx.x >> 5;
    const float* xb = x + ((size_t)b * C_ + k0) * N_ + m0;
#pragma unroll
    for (int q = 0; q < 4; q++) t[ty + q * 8][tx] = xb[(size_t)(ty + q * 8) * N_ + tx];
    __syncthreads();
    for (int it = threadIdx.x; it < 512; it += 256) {
        int mp = it >> 4, kp = it & 15;
        unsigned hi, lo;
        split2(t[kp * 2][mp], t[kp * 2 + 1][mp], hi, lo);
        size_t idx = ((size_t)b * N_ + m0 + mp) * CP + (k0 >> 1) + kp;
        g_xT_hi[idx] = hi; g_xT_lo[idx] = lo;
    }
}

// ---------------- pre-kernel 2: split weights ----------------
__global__ __launch_bounds__(256) void split_w(const float* __restrict__ wq,
                                               const float* __restrict__ wp) {
    const int NQ = O3 * CP, NP = C_ * CP;
    int i = blockIdx.x * 256 + threadIdx.x;
    if (i < NQ) {
        float2 f = *(const float2*)(wq + 2 * (size_t)i);
        unsigned hi, lo; split2(f.x, f.y, hi, lo);
        g_wq_hi[i] = hi; g_wq_lo[i] = lo;
    } else if (i < NQ + NP) {
        int j = i - NQ;
        float2 f = *(const float2*)(wp + 2 * (size_t)j);
        unsigned hi, lo; split2(f.x, f.y, hi, lo);
        g_wp_hi[j] = hi; g_wp_lo[j] = lo;
    }
}

// ---------------- GEMM: C[m][n] = sum_k A[m][k]*B[n][k], bf16-split mma ----
// Block 128m x 64n, 256 threads (8 warps, 4m x 2n). K-chunk 32. LDSM fragments.
template <int EPI>
__global__ __launch_bounds__(256) void gemm_bf16(const float* __restrict__ bias,
                                                 float* __restrict__ out) {
    __shared__ unsigned As_h[128 * 20], As_l[128 * 20];
    __shared__ unsigned Bs_h[64 * 20],  Bs_l[64 * 20];

    const unsigned* Ah = EPI ? g_att_hi : g_xT_hi;
    const unsigned* Al = EPI ? g_att_lo : g_xT_lo;
    const unsigned* Bh = EPI ? g_wp_hi  : g_wq_hi;
    const unsigned* Bl = EPI ? g_wp_lo  : g_wq_lo;

    const int b = blockIdx.z;
    const int m0 = blockIdx.y * 128, n0 = blockIdx.x * 64;
    const int tid = threadIdx.x, lane = tid & 31, wid = tid >> 5;
    const int wm = (wid >> 1) * 32, wn = (wid & 1) * 32;
    const int r = lane >> 2, c = lane & 3;

    float acc[2][4][4] = {};

    const int arow = tid >> 1, ahalf = tid & 1;
    const int brow = tid >> 2, bq = tid & 3;
    const unsigned* agp = Ah + ((size_t)(b * N_ + m0 + arow)) * CP + ahalf * 8;
    const unsigned* agl = Al + ((size_t)(b * N_ + m0 + arow)) * CP + ahalf * 8;
    const unsigned* bgp = Bh + (size_t)(n0 + brow) * CP + bq * 4;
    const unsigned* bgl = Bl + (size_t)(n0 + brow) * CP + bq * 4;

    // LDSM base addresses (byte offsets into shared)
    const unsigned offA = ((wm + (lane & 15)) * 20 + (lane >> 4) * 4) * 4;
    const unsigned baseAh = smem_u32p(As_h) + offA;
    const unsigned baseAl = smem_u32p(As_l) + offA;
    const unsigned offB = ((wn + (lane & 7) + ((lane >> 4) << 3)) * 20 +
                           ((lane >> 3) & 1) * 4) * 4;
    const unsigned baseBh = smem_u32p(Bs_h) + offB;
    const unsigned baseBl = smem_u32p(Bs_l) + offB;

    for (int kc = 0; kc < 12; kc++) {
        __syncthreads();
        {
            uint4 v0 = *(const uint4*)(agp + kc * 16);
            uint4 v1 = *(const uint4*)(agp + kc * 16 + 4);
            *(uint4*)&As_h[arow * 20 + ahalf * 8]     = v0;
            *(uint4*)&As_h[arow * 20 + ahalf * 8 + 4] = v1;
            uint4 u0 = *(const uint4*)(agl + kc * 16);
            uint4 u1 = *(const uint4*)(agl + kc * 16 + 4);
            *(uint4*)&As_l[arow * 20 + ahalf * 8]     = u0;
            *(uint4*)&As_l[arow * 20 + ahalf * 8 + 4] = u1;
            uint4 w0 = *(const uint4*)(bgp + kc * 16);
            *(uint4*)&Bs_h[brow * 20 + bq * 4] = w0;
            uint4 w1 = *(const uint4*)(bgl + kc * 16);
            *(uint4*)&Bs_l[brow * 20 + bq * 4] = w1;
        }
        __syncthreads();

#pragma unroll
        for (int ks = 0; ks < 2; ks++) {
            unsigned ah[2][4], al[2][4];
#pragma unroll
            for (int mt = 0; mt < 2; mt++) {
                ldsm_x4(ah[mt][0], ah[mt][1], ah[mt][2], ah[mt][3],
                        baseAh + mt * 1280 + ks * 32);
                ldsm_x4(al[mt][0], al[mt][1], al[mt][2], al[mt][3],
                        baseAl + mt * 1280 + ks * 32);
            }
#pragma unroll
            for (int tp = 0; tp < 2; tp++) {
                unsigned bh[4], bl[4];
                ldsm_x4(bh[0], bh[1], bh[2], bh[3], baseBh + tp * 1280 + ks * 32);
                ldsm_x4(bl[0], bl[1], bl[2], bl[3], baseBl + tp * 1280 + ks * 32);
#pragma unroll
                for (int mt = 0; mt < 2; mt++) {
                    mma16816(acc[mt][2 * tp],     ah[mt], &bh[0]);
                    mma16816(acc[mt][2 * tp],     al[mt], &bh[0]);
                    mma16816(acc[mt][2 * tp],     ah[mt], &bl[0]);
                    mma16816(acc[mt][2 * tp + 1], ah[mt], &bh[2]);
                    mma16816(acc[mt][2 * tp + 1], al[mt], &bh[2]);
                    mma16816(acc[mt][2 * tp + 1], ah[mt], &bl[2]);
                }
            }
        }
    }

    if (EPI == 0) {
#pragma unroll
        for (int mt = 0; mt < 2; mt++)
#pragma unroll
            for (int nt = 0; nt < 4; nt++) {
                int m = m0 + wm + mt * 16 + r;
                int colp = (n0 >> 1) + (wn >> 1) + nt * 4 + c;
                unsigned hi, lo;
                split2(acc[mt][nt][0], acc[mt][nt][1], hi, lo);
                g_qkv_hi[(size_t)(b * N_ + m) * O3P + colp] = hi;
                g_qkv_lo[(size_t)(b * N_ + m) * O3P + colp] = lo;
                split2(acc[mt][nt][2], acc[mt][nt][3], hi, lo);
                g_qkv_hi[(size_t)(b * N_ + m + 8) * O3P + colp] = hi;
                g_qkv_lo[(size_t)(b * N_ + m + 8) * O3P + colp] = lo;
            }
    } else {
#pragma unroll
        for (int mt = 0; mt < 2; mt++)
#pragma unroll
            for (int nt = 0; nt < 4; nt++)
#pragma unroll
                for (int q = 0; q < 4; q++) {
                    int o = n0 + wn + nt * 8 + 2 * c + (q & 1);
                    int m = m0 + wm + mt * 16 + r + ((q >> 1) * 8);
                    out[((size_t)b * C_ + o) * N_ + m] = acc[mt][nt][q] + bias[o];
                }
    }
}

// ---------------- flash attention, bf16-split mma + LDSM ----------------
// Block = 128 queries of one (b,h), 256 threads (8 warps x 16 rows).
__global__ __launch_bounds__(256) void attn_bf16() {
    __shared__ unsigned Ks_h[64 * 20], Ks_l[64 * 20];
    __shared__ unsigned Vs_h[32 * 36], Vs_l[32 * 36];

    const int tid = threadIdx.x, lane = tid & 31, wid = tid >> 5;
    const int bh = blockIdx.y, b = bh / NH, h = bh % NH;
    const int i0 = blockIdx.x * 128;
    const int iw = i0 + wid * 16;
    const int r = lane >> 2, c = lane & 3;

    // Q fragments, loaded once from global
    unsigned qh[2][4], ql[2][4];
    {
        const unsigned* qb_h = g_qkv_hi + (size_t)(b * N_ + iw) * O3P + h * 16;
        const unsigned* qb_l = g_qkv_lo + (size_t)(b * N_ + iw) * O3P + h * 16;
#pragma unroll
        for (int ks = 0; ks < 2; ks++) {
            qh[ks][0] = qb_h[(size_t)r * O3P + ks * 8 + c];
            qh[ks][1] = qb_h[(size_t)(r + 8) * O3P + ks * 8 + c];
            qh[ks][2] = qb_h[(size_t)r * O3P + ks * 8 + 4 + c];
            qh[ks][3] = qb_h[(size_t)(r + 8) * O3P + ks * 8 + 4 + c];
            ql[ks][0] = qb_l[(size_t)r * O3P + ks * 8 + c];
            ql[ks][1] = qb_l[(size_t)(r + 8) * O3P + ks * 8 + c];
            ql[ks][2] = qb_l[(size_t)r * O3P + ks * 8 + 4 + c];
            ql[ks][3] = qb_l[(size_t)(r + 8) * O3P + ks * 8 + 4 + c];
        }
    }

    // LDSM base offsets
    const unsigned offK = (((lane & 7) + ((lane >> 4) << 3)) * 20 +
                           ((lane >> 3) & 1) * 4) * 4;
    const unsigned baseKh = smem_u32p(Ks_h) + offK;
    const unsigned baseKl = smem_u32p(Ks_l) + offK;
    const unsigned offV = (((lane & 7) + ((lane >> 4) << 3)) * 36 +
                           ((lane >> 3) & 1) * 4) * 4;
    const unsigned baseVh = smem_u32p(Vs_h) + offV;
    const unsigned baseVl = smem_u32p(Vs_l) + offV;

    float m_run[2] = {-1e30f, -1e30f}, l_run[2] = {0.f, 0.f};
    float acc_o[4][4] = {};

    for (int jt = 0; jt < 16; jt++) {
        __syncthreads();
        {   // stage K tile [j=64][dpair=16] hi/lo  (256 tasks)
            int row = tid >> 2, half = (tid >> 1) & 1, hl = tid & 1;
            const unsigned* sp = (hl ? g_qkv_lo : g_qkv_hi) +
                (size_t)(b * N_ + jt * 64 + row) * O3P + 192 + h * 16 + half * 8;
            unsigned* dp = (hl ? Ks_l : Ks_h) + row * 20 + half * 8;
            uint4 v0 = ((const uint4*)sp)[0];
            uint4 v1 = ((const uint4*)sp)[1];
            ((uint4*)dp)[0] = v0;
            ((uint4*)dp)[1] = v1;
        }
        {   // stage V tile transposed -> [d=32][jpair=32] hi/lo (256 tasks)
            int jp = tid & 31, dg = (tid >> 5) & 3, hl = tid >> 7;
            const unsigned* sp = (hl ? g_qkv_lo : g_qkv_hi) +
                (size_t)(b * N_ + jt * 64 + jp * 2) * O3P + 384 + h * 16 + dg * 4;
            unsigned* Vd = hl ? Vs_l : Vs_h;
            uint4 va = *(const uint4*)sp, vb = *(const uint4*)(sp + O3P);
            unsigned aw[4] = {va.x, va.y, va.z, va.w};
            unsigned bw[4] = {vb.x, vb.y, vb.z, vb.w};
#pragma unroll
            for (int e = 0; e < 8; e++)
                Vd[(dg * 8 + e) * 36 + jp] =
                    __byte_perm(aw[e >> 1], bw[e >> 1], (e & 1) ? 0x7632 : 0x5410);
        }
        __syncthreads();

        // S = Q K^T   (LDSM fragments, two j-tiles per x4)
        float s[8][4] = {};
#pragma unroll
        for (int ks = 0; ks < 2; ks++)
#pragma unroll
            for (int tp = 0; tp < 4; tp++) {
                unsigned kh[4], kl[4];
                ldsm_x4(kh[0], kh[1], kh[2], kh[3], baseKh + tp * 1280 + ks * 32);
                ldsm_x4(kl[0], kl[1], kl[2], kl[3], baseKl + tp * 1280 + ks * 32);
                mma16816(s[2 * tp],     qh[ks], &kh[0]);
                mma16816(s[2 * tp],     ql[ks], &kh[0]);
                mma16816(s[2 * tp],     qh[ks], &kl[0]);
                mma16816(s[2 * tp + 1], qh[ks], &kh[2]);
                mma16816(s[2 * tp + 1], ql[ks], &kh[2]);
                mma16816(s[2 * tp + 1], qh[ks], &kl[2]);
            }

        // online softmax (rows r and r+8; each row shared by 4 lanes)
        float mx0 = m_run[0], mx1 = m_run[1];
#pragma unroll
        for (int nt = 0; nt < 8; nt++) {
            s[nt][0] *= SCALE; s[nt][1] *= SCALE; s[nt][2] *= SCALE; s[nt][3] *= SCALE;
            mx0 = fmaxf(mx0, fmaxf(s[nt][0], s[nt][1]));
            mx1 = fmaxf(mx1, fmaxf(s[nt][2], s[nt][3]));
        }
        mx0 = fmaxf(mx0, __shfl_xor_sync(0xffffffffu, mx0, 1));
        mx0 = fmaxf(mx0, __shfl_xor_sync(0xffffffffu, mx0, 2));
        mx1 = fmaxf(mx1, __shfl_xor_sync(0xffffffffu, mx1, 1));
        mx1 = fmaxf(mx1, __shfl_xor_sync(0xffffffffu, mx1, 2));
        float corr0 = __expf(m_run[0] - mx0);
        float corr1 = __expf(m_run[1] - mx1);
        float rs0 = 0.f, rs1 = 0.f;
#pragma unroll
        for (int nt = 0; nt < 8; nt++) {
            s[nt][0] = __expf(s[nt][0] - mx0);
            s[nt][1] = __expf(s[nt][1] - mx0);
            s[nt][2] = __expf(s[nt][2] - mx1);
            s[nt][3] = __expf(s[nt][3] - mx1);
            rs0 += s[nt][0] + s[nt][1];
            rs1 += s[nt][2] + s[nt][3];
        }
        rs0 += __shfl_xor_sync(0xffffffffu, rs0, 1);
        rs0 += __shfl_xor_sync(0xffffffffu, rs0, 2);
        rs1 += __shfl_xor_sync(0xffffffffu, rs1, 1);
        rs1 += __shfl_xor_sync(0xffffffffu, rs1, 2);
        l_run[0] = l_run[0] * corr0 + rs0;
        l_run[1] = l_run[1] * corr1 + rs1;
        m_run[0] = mx0; m_run[1] = mx1;
#pragma unroll
        for (int nt = 0; nt < 4; nt++) {
            acc_o[nt][0] *= corr0; acc_o[nt][1] *= corr0;
            acc_o[nt][2] *= corr1; acc_o[nt][3] *= corr1;
        }

        // O += P V  (P from registers; V fragments via LDSM, 2 d-tiles per x4)
#pragma unroll
        for (int kk = 0; kk < 4; kk++) {
            unsigned ph[4], pl[4];
            split2(s[2 * kk][0],     s[2 * kk][1],     ph[0], pl[0]);
            split2(s[2 * kk][2],     s[2 * kk][3],     ph[1], pl[1]);
            split2(s[2 * kk + 1][0], s[2 * kk + 1][1], ph[2], pl[2]);
            split2(s[2 * kk + 1][2], s[2 * kk + 1][3], ph[3], pl[3]);
#pragma unroll
            for (int tp = 0; tp < 2; tp++) {
                unsigned vh[4], vl[4];
                ldsm_x4(vh[0], vh[1], vh[2], vh[3], baseVh + tp * 2304 + kk * 32);
                ldsm_x4(vl[0], vl[1], vl[2], vl[3], baseVl + tp * 2304 + kk * 32);
                mma16816(acc_o[2 * tp],     ph, &vh[0]);
                mma16816(acc_o[2 * tp],     pl, &vh[0]);
                mma16816(acc_o[2 * tp],     ph, &vl[0]);
                mma16816(acc_o[2 * tp + 1], ph, &vh[2]);
                mma16816(acc_o[2 * tp + 1], pl, &vh[2]);
                mma16816(acc_o[2 * tp + 1], ph, &vl[2]);
            }
        }
    }

    // epilogue: normalize, split to bf16 hi/lo, store att
    float inv0 = 1.0f / l_run[0], inv1 = 1.0f / l_run[1];
#pragma unroll
    for (int nt = 0; nt < 4; nt++) {
        unsigned hi, lo;
        split2(acc_o[nt][0] * inv0, acc_o[nt][1] * inv0, hi, lo);
        size_t idx0 = (size_t)(b * N_ + iw + r) * CP + h * 16 + nt * 4 + c;
        g_att_hi[idx0] = hi; g_att_lo[idx0] = lo;
        split2(acc_o[nt][2] * inv1, acc_o[nt][3] * inv1, hi, lo);
        size_t idx1 = (size_t)(b * N_ + iw + r + 8) * CP + h * 16 + nt * 4 + c;
        g_att_hi[idx1] = hi; g_att_lo[idx1] = lo;
    }
}

// ---------------------------------------------------------------------------
extern "C" void kernel_launch(void* const* d_in, const int* in_sizes, int n_in,
                              void* d_out, int out_size) {
    const float* x     = (const float*)d_in[0];
    const float* W_qkv = (const float*)d_in[1];
    const float* W_prj = (const float*)d_in[2];
    const float* b_prj = (const float*)d_in[3];
    float* out = (float*)d_out;
    (void)in_sizes; (void)n_in; (void)out_size;

    dim3 gt(C_ / 32, N_ / 32, B_);           // 12 x 32 x 8
    split_x<<<gt, 256>>>(x);

    split_w<<<(O3 * CP + C_ * CP + 255) / 256, 256>>>(W_qkv, W_prj);

    dim3 g1(O3 / 64, N_ / 128, B_);          // 18 x 8 x 8
    gemm_bf16<0><<<g1, 256>>>(nullptr, nullptr);

    dim3 g2(N_ / 128, B_ * NH);              // 8 x 96
    attn_bf16<<<g2, 256>>>();

    dim3 g3(C_ / 64, N_ / 128, B_);          // 6 x 8 x 8
    gemm_bf16<1><<<g3, 256>>>(b_prj, out);
}

// round 4
// speedup vs baseline: 2.7053x; 1.1929x over previous
#include <cuda_runtime.h>
#include <cuda_bf16.h>
#include <math.h>

#define B_    8
#define NH    12
#define N_    1024
#define C_    384
#define CP    192       // C/2 (bf16x2 pairs per row)
#define O3    1152
#define O3P   576       // O3/2
#define SCALE 0.17677669529663687f

// ---------------- scratch (bf16x2 packed as u32) ----------------
static __device__ unsigned g_xT_hi[B_ * N_ * CP];
static __device__ unsigned g_xT_lo[B_ * N_ * CP];
static __device__ unsigned g_wq_hi[O3 * CP];
static __device__ unsigned g_wq_lo[O3 * CP];
static __device__ unsigned g_wp_hi[C_ * CP];
static __device__ unsigned g_wp_lo[C_ * CP];
static __device__ unsigned g_qkv_hi[B_ * N_ * O3P];
static __device__ unsigned g_qkv_lo[B_ * N_ * O3P];
static __device__ unsigned g_att_hi[B_ * N_ * CP];
static __device__ unsigned g_att_lo[B_ * N_ * CP];

__device__ __forceinline__ void split2(float f0, float f1, unsigned& hi, unsigned& lo) {
    unsigned h, l;
    asm("cvt.rn.bf16x2.f32 %0, %1, %2;" : "=r"(h) : "f"(f1), "f"(f0));
    float h0 = __uint_as_float(h << 16);
    float h1 = __uint_as_float(h & 0xffff0000u);
    float r0 = f0 - h0, r1 = f1 - h1;
    asm("cvt.rn.bf16x2.f32 %0, %1, %2;" : "=r"(l) : "f"(r1), "f"(r0));
    hi = h; lo = l;
}

__device__ __forceinline__ void mma16816(float* d, const unsigned* a, const unsigned* b) {
    asm volatile(
        "mma.sync.aligned.m16n8k16.row.col.f32.bf16.bf16.f32 "
        "{%0,%1,%2,%3}, {%4,%5,%6,%7}, {%8,%9}, {%0,%1,%2,%3};"
        : "+f"(d[0]), "+f"(d[1]), "+f"(d[2]), "+f"(d[3])
        : "r"(a[0]), "r"(a[1]), "r"(a[2]), "r"(a[3]), "r"(b[0]), "r"(b[1]));
}

__device__ __forceinline__ unsigned smem_u32p(const void* p) {
    return (unsigned)__cvta_generic_to_shared(p);
}

__device__ __forceinline__ void ldsm_x4(unsigned& r0, unsigned& r1,
                                        unsigned& r2, unsigned& r3, unsigned addr) {
    asm volatile("ldmatrix.sync.aligned.m8n8.x4.shared.b16 {%0,%1,%2,%3}, [%4];"
                 : "=r"(r0), "=r"(r1), "=r"(r2), "=r"(r3) : "r"(addr));
}

__device__ __forceinline__ void ldsm_x4_t(unsigned& r0, unsigned& r1,
                                          unsigned& r2, unsigned& r3, unsigned addr) {
    asm volatile("ldmatrix.sync.aligned.m8n8.x4.trans.shared.b16 {%0,%1,%2,%3}, [%4];"
                 : "=r"(r0), "=r"(r1), "=r"(r2), "=r"(r3) : "r"(addr));
}

__device__ __forceinline__ void cp16(unsigned dst, const void* src) {
    asm volatile("cp.async.cg.shared.global [%0], [%1], 16;" :: "r"(dst), "l"(src));
}
__device__ __forceinline__ void cp_commit() {
    asm volatile("cp.async.commit_group;" ::: "memory");
}
__device__ __forceinline__ void cp_wait0() {
    asm volatile("cp.async.wait_group 0;" ::: "memory");
}

// ---------------- pre-kernel 1: transpose + split x -> xT ----------------
__global__ __launch_bounds__(256) void split_x(const float* __restrict__ x) {
    __shared__ float t[32][33];
    const int k0 = blockIdx.x * 32, m0 = blockIdx.y * 32, b = blockIdx.z;
    const int tx = threadIdx.x & 31, ty = threadIdx.x >> 5;
    const float* xb = x + ((size_t)b * C_ + k0) * N_ + m0;
#pragma unroll
    for (int q = 0; q < 4; q++) t[ty + q * 8][tx] = xb[(size_t)(ty + q * 8) * N_ + tx];
    __syncthreads();
    for (int it = threadIdx.x; it < 512; it += 256) {
        int mp = it >> 4, kp = it & 15;
        unsigned hi, lo;
        split2(t[kp * 2][mp], t[kp * 2 + 1][mp], hi, lo);
        size_t idx = ((size_t)b * N_ + m0 + mp) * CP + (k0 >> 1) + kp;
        g_xT_hi[idx] = hi; g_xT_lo[idx] = lo;
    }
}

// ---------------- pre-kernel 2: split weights ----------------
__global__ __launch_bounds__(256) void split_w(const float* __restrict__ wq,
                                               const float* __restrict__ wp) {
    const int NQ = O3 * CP, NP = C_ * CP;
    int i = blockIdx.x * 256 + threadIdx.x;
    if (i < NQ) {
        float2 f = *(const float2*)(wq + 2 * (size_t)i);
        unsigned hi, lo; split2(f.x, f.y, hi, lo);
        g_wq_hi[i] = hi; g_wq_lo[i] = lo;
    } else if (i < NQ + NP) {
        int j = i - NQ;
        float2 f = *(const float2*)(wp + 2 * (size_t)j);
        unsigned hi, lo; split2(f.x, f.y, hi, lo);
        g_wp_hi[j] = hi; g_wp_lo[j] = lo;
    }
}

// ---------------- GEMM, double-buffered cp.async + LDSM ----------------
template <int EPI>
__global__ __launch_bounds__(256) void gemm_bf16(const float* __restrict__ bias,
                                                 float* __restrict__ out) {
    __shared__ unsigned As_h[2][2560], As_l[2][2560];   // 128 x 20
    __shared__ unsigned Bs_h[2][1280], Bs_l[2][1280];   // 64 x 20

    const unsigned* Ah = EPI ? g_att_hi : g_xT_hi;
    const unsigned* Al = EPI ? g_att_lo : g_xT_lo;
    const unsigned* Bh = EPI ? g_wp_hi  : g_wq_hi;
    const unsigned* Bl = EPI ? g_wp_lo  : g_wq_lo;

    const int b = blockIdx.z;
    const int m0 = blockIdx.y * 128, n0 = blockIdx.x * 64;
    const int tid = threadIdx.x, lane = tid & 31, wid = tid >> 5;
    const int wm = (wid >> 1) * 32, wn = (wid & 1) * 32;
    const int r = lane >> 2, c = lane & 3;

    float acc[2][4][4] = {};

    const int arow = tid >> 1, ahalf = tid & 1;
    const int brow = tid >> 2, bq = tid & 3;
    const unsigned* agp = Ah + ((size_t)(b * N_ + m0 + arow)) * CP + ahalf * 8;
    const unsigned* agl = Al + ((size_t)(b * N_ + m0 + arow)) * CP + ahalf * 8;
    const unsigned* bgp = Bh + (size_t)(n0 + brow) * CP + bq * 4;
    const unsigned* bgl = Bl + (size_t)(n0 + brow) * CP + bq * 4;

    const unsigned dAh0 = smem_u32p(&As_h[0][arow * 20 + ahalf * 8]);
    const unsigned dAl0 = smem_u32p(&As_l[0][arow * 20 + ahalf * 8]);
    const unsigned dBh0 = smem_u32p(&Bs_h[0][brow * 20 + bq * 4]);
    const unsigned dBl0 = smem_u32p(&Bs_l[0][brow * 20 + bq * 4]);

    const unsigned offA = ((wm + (lane & 15)) * 20 + (lane >> 4) * 4) * 4;
    const unsigned baseAh = smem_u32p(As_h) + offA;
    const unsigned baseAl = smem_u32p(As_l) + offA;
    const unsigned offB = ((wn + (lane & 7) + ((lane >> 4) << 3)) * 20 +
                           ((lane >> 3) & 1) * 4) * 4;
    const unsigned baseBh = smem_u32p(Bs_h) + offB;
    const unsigned baseBl = smem_u32p(Bs_l) + offB;

#define GEMM_STAGE(kc, sel)                                             \
    do {                                                                \
        unsigned so = (sel) * 10240, sob = (sel) * 5120;                \
        cp16(dAh0 + so,      agp + (kc) * 16);                          \
        cp16(dAh0 + so + 16, agp + (kc) * 16 + 4);                      \
        cp16(dAl0 + so,      agl + (kc) * 16);                          \
        cp16(dAl0 + so + 16, agl + (kc) * 16 + 4);                      \
        cp16(dBh0 + sob,     bgp + (kc) * 16);                          \
        cp16(dBl0 + sob,     bgl + (kc) * 16);                          \
    } while (0)

    GEMM_STAGE(0, 0);
    cp_commit();

    for (int kc = 0; kc < 12; kc++) {
        const int sel = kc & 1;
        cp_wait0();
        __syncthreads();
        if (kc < 11) { GEMM_STAGE(kc + 1, sel ^ 1); cp_commit(); }

        const unsigned sa = sel * 10240, sb = sel * 5120;
#pragma unroll
        for (int ks = 0; ks < 2; ks++) {
            unsigned ah[2][4], al[2][4];
#pragma unroll
            for (int mt = 0; mt < 2; mt++) {
                ldsm_x4(ah[mt][0], ah[mt][1], ah[mt][2], ah[mt][3],
                        baseAh + sa + mt * 1280 + ks * 32);
                ldsm_x4(al[mt][0], al[mt][1], al[mt][2], al[mt][3],
                        baseAl + sa + mt * 1280 + ks * 32);
            }
#pragma unroll
            for (int tp = 0; tp < 2; tp++) {
                unsigned bh[4], bl[4];
                ldsm_x4(bh[0], bh[1], bh[2], bh[3], baseBh + sb + tp * 1280 + ks * 32);
                ldsm_x4(bl[0], bl[1], bl[2], bl[3], baseBl + sb + tp * 1280 + ks * 32);
#pragma unroll
                for (int mt = 0; mt < 2; mt++) {
                    mma16816(acc[mt][2 * tp],     ah[mt], &bh[0]);
                    mma16816(acc[mt][2 * tp],     al[mt], &bh[0]);
                    mma16816(acc[mt][2 * tp],     ah[mt], &bl[0]);
                    mma16816(acc[mt][2 * tp + 1], ah[mt], &bh[2]);
                    mma16816(acc[mt][2 * tp + 1], al[mt], &bh[2]);
                    mma16816(acc[mt][2 * tp + 1], ah[mt], &bl[2]);
                }
            }
        }
    }

    if (EPI == 0) {
#pragma unroll
        for (int mt = 0; mt < 2; mt++)
#pragma unroll
            for (int nt = 0; nt < 4; nt++) {
                int m = m0 + wm + mt * 16 + r;
                int colp = (n0 >> 1) + (wn >> 1) + nt * 4 + c;
                unsigned hi, lo;
                split2(acc[mt][nt][0], acc[mt][nt][1], hi, lo);
                g_qkv_hi[(size_t)(b * N_ + m) * O3P + colp] = hi;
                g_qkv_lo[(size_t)(b * N_ + m) * O3P + colp] = lo;
                split2(acc[mt][nt][2], acc[mt][nt][3], hi, lo);
                g_qkv_hi[(size_t)(b * N_ + m + 8) * O3P + colp] = hi;
                g_qkv_lo[(size_t)(b * N_ + m + 8) * O3P + colp] = lo;
            }
    } else {
#pragma unroll
        for (int mt = 0; mt < 2; mt++)
#pragma unroll
            for (int nt = 0; nt < 4; nt++)
#pragma unroll
                for (int q = 0; q < 4; q++) {
                    int o = n0 + wn + nt * 8 + 2 * c + (q & 1);
                    int m = m0 + wm + mt * 16 + r + ((q >> 1) * 8);
                    out[((size_t)b * C_ + o) * N_ + m] = acc[mt][nt][q] + bias[o];
                }
    }
}

// ---------------- flash attention: cp.async double-buffer + LDSM(+trans) ---
// Block = 128 queries of one (b,h), 256 threads (8 warps x 16 rows).
__global__ __launch_bounds__(256) void attn_bf16() {
    __shared__ unsigned Ks_h[2][1280], Ks_l[2][1280];   // [j=64][20], K: [j][dpair]
    __shared__ unsigned Vs_h[2][1280], Vs_l[2][1280];   // [j=64][20], V: [j][d bf16]

    const int tid = threadIdx.x, lane = tid & 31, wid = tid >> 5;
    const int bh = blockIdx.y, b = bh / NH, h = bh % NH;
    const int i0 = blockIdx.x * 128;
    const int iw = i0 + wid * 16;
    const int r = lane >> 2, c = lane & 3;

    // Q fragments (global, once)
    unsigned qh[2][4], ql[2][4];
    {
        const unsigned* qb_h = g_qkv_hi + (size_t)(b * N_ + iw) * O3P + h * 16;
        const unsigned* qb_l = g_qkv_lo + (size_t)(b * N_ + iw) * O3P + h * 16;
#pragma unroll
        for (int ks = 0; ks < 2; ks++) {
            qh[ks][0] = qb_h[(size_t)r * O3P + ks * 8 + c];
            qh[ks][1] = qb_h[(size_t)(r + 8) * O3P + ks * 8 + c];
            qh[ks][2] = qb_h[(size_t)r * O3P + ks * 8 + 4 + c];
            qh[ks][3] = qb_h[(size_t)(r + 8) * O3P + ks * 8 + 4 + c];
            ql[ks][0] = qb_l[(size_t)r * O3P + ks * 8 + c];
            ql[ks][1] = qb_l[(size_t)(r + 8) * O3P + ks * 8 + c];
            ql[ks][2] = qb_l[(size_t)r * O3P + ks * 8 + 4 + c];
            ql[ks][3] = qb_l[(size_t)(r + 8) * O3P + ks * 8 + 4 + c];
        }
    }

    // staging: row = tid>>2, q = tid&3 (one 16B chunk per array)
    const int srow = tid >> 2, sq = tid & 3;
    const size_t srcK = (size_t)(b * N_ + srow) * O3P + 192 + h * 16 + sq * 4;
    const size_t srcV = (size_t)(b * N_ + srow) * O3P + 384 + h * 16 + sq * 4;
    const unsigned dK = smem_u32p(&Ks_h[0][srow * 20 + sq * 4]);
    const unsigned dKl = smem_u32p(&Ks_l[0][srow * 20 + sq * 4]);
    const unsigned dV = smem_u32p(&Vs_h[0][srow * 20 + sq * 4]);
    const unsigned dVl = smem_u32p(&Vs_l[0][srow * 20 + sq * 4]);

#define ATTN_STAGE(jt, sel)                                            \
    do {                                                               \
        size_t ro = (size_t)(jt) * 64 * O3P;                           \
        unsigned so = (sel) * 5120;                                    \
        cp16(dK  + so, g_qkv_hi + srcK + ro);                          \
        cp16(dKl + so, g_qkv_lo + srcK + ro);                          \
        cp16(dV  + so, g_qkv_hi + srcV + ro);                          \
        cp16(dVl + so, g_qkv_lo + srcV + ro);                          \
    } while (0)

    // LDSM bases
    const unsigned offK = (((lane & 7) + ((lane >> 4) << 3)) * 20 +
                           ((lane >> 3) & 1) * 4) * 4;
    const unsigned baseKh = smem_u32p(Ks_h) + offK;
    const unsigned baseKl = smem_u32p(Ks_l) + offK;
    // V trans: group g=lane>>3: j = (g&1)*8 + (lane&7), d-col = (g>>1)*8
    const unsigned offV = (((lane >> 3) & 1) * 8 + (lane & 7)) * 80 +
                          (lane >> 4) * 16;
    const unsigned baseVh = smem_u32p(Vs_h) + offV;
    const unsigned baseVl = smem_u32p(Vs_l) + offV;

    float m_run[2] = {-1e30f, -1e30f}, l_run[2] = {0.f, 0.f};
    float acc_o[4][4] = {};

    ATTN_STAGE(0, 0);
    cp_commit();

    for (int jt = 0; jt < 16; jt++) {
        const int sel = jt & 1;
        cp_wait0();
        __syncthreads();
        if (jt < 15) { ATTN_STAGE(jt + 1, sel ^ 1); cp_commit(); }

        const unsigned so = sel * 5120;

        // S = Q K^T
        float s[8][4] = {};
#pragma unroll
        for (int ks = 0; ks < 2; ks++)
#pragma unroll
            for (int tp = 0; tp < 4; tp++) {
                unsigned kh[4], kl[4];
                ldsm_x4(kh[0], kh[1], kh[2], kh[3], baseKh + so + tp * 1280 + ks * 32);
                ldsm_x4(kl[0], kl[1], kl[2], kl[3], baseKl + so + tp * 1280 + ks * 32);
                mma16816(s[2 * tp],     qh[ks], &kh[0]);
                mma16816(s[2 * tp],     ql[ks], &kh[0]);
                mma16816(s[2 * tp],     qh[ks], &kl[0]);
                mma16816(s[2 * tp + 1], qh[ks], &kh[2]);
                mma16816(s[2 * tp + 1], ql[ks], &kh[2]);
                mma16816(s[2 * tp + 1], qh[ks], &kl[2]);
            }

        // online softmax
        float mx0 = m_run[0], mx1 = m_run[1];
#pragma unroll
        for (int nt = 0; nt < 8; nt++) {
            s[nt][0] *= SCALE; s[nt][1] *= SCALE; s[nt][2] *= SCALE; s[nt][3] *= SCALE;
            mx0 = fmaxf(mx0, fmaxf(s[nt][0], s[nt][1]));
            mx1 = fmaxf(mx1, fmaxf(s[nt][2], s[nt][3]));
        }
        mx0 = fmaxf(mx0, __shfl_xor_sync(0xffffffffu, mx0, 1));
        mx0 = fmaxf(mx0, __shfl_xor_sync(0xffffffffu, mx0, 2));
        mx1 = fmaxf(mx1, __shfl_xor_sync(0xffffffffu, mx1, 1));
        mx1 = fmaxf(mx1, __shfl_xor_sync(0xffffffffu, mx1, 2));
        float corr0 = __expf(m_run[0] - mx0);
        float corr1 = __expf(m_run[1] - mx1);
        float rs0 = 0.f, rs1 = 0.f;
#pragma unroll
        for (int nt = 0; nt < 8; nt++) {
            s[nt][0] = __expf(s[nt][0] - mx0);
            s[nt][1] = __expf(s[nt][1] - mx0);
            s[nt][2] = __expf(s[nt][2] - mx1);
            s[nt][3] = __expf(s[nt][3] - mx1);
            rs0 += s[nt][0] + s[nt][1];
            rs1 += s[nt][2] + s[nt][3];
        }
        rs0 += __shfl_xor_sync(0xffffffffu, rs0, 1);
        rs0 += __shfl_xor_sync(0xffffffffu, rs0, 2);
        rs1 += __shfl_xor_sync(0xffffffffu, rs1, 1);
        rs1 += __shfl_xor_sync(0xffffffffu, rs1, 2);
        l_run[0] = l_run[0] * corr0 + rs0;
        l_run[1] = l_run[1] * corr1 + rs1;
        m_run[0] = mx0; m_run[1] = mx1;
#pragma unroll
        for (int nt = 0; nt < 4; nt++) {
            acc_o[nt][0] *= corr0; acc_o[nt][1] *= corr0;
            acc_o[nt][2] *= corr1; acc_o[nt][3] *= corr1;
        }

        // O += P V   (V B-fragments via ldmatrix.trans on [j][d] tile)
#pragma unroll
        for (int kk = 0; kk < 4; kk++) {
            unsigned ph[4], pl[4];
            split2(s[2 * kk][0],     s[2 * kk][1],     ph[0], pl[0]);
            split2(s[2 * kk][2],     s[2 * kk][3],     ph[1], pl[1]);
            split2(s[2 * kk + 1][0], s[2 * kk + 1][1], ph[2], pl[2]);
            split2(s[2 * kk + 1][2], s[2 * kk + 1][3], ph[3], pl[3]);
#pragma unroll
            for (int tp = 0; tp < 2; tp++) {
                unsigned vh[4], vl[4];
                ldsm_x4_t(vh[0], vh[1], vh[2], vh[3],
                          baseVh + so + kk * 1280 + tp * 32);
                ldsm_x4_t(vl[0], vl[1], vl[2], vl[3],
                          baseVl + so + kk * 1280 + tp * 32);
                mma16816(acc_o[2 * tp],     ph, &vh[0]);
                mma16816(acc_o[2 * tp],     pl, &vh[0]);
                mma16816(acc_o[2 * tp],     ph, &vl[0]);
                mma16816(acc_o[2 * tp + 1], ph, &vh[2]);
                mma16816(acc_o[2 * tp + 1], pl, &vh[2]);
                mma16816(acc_o[2 * tp + 1], ph, &vl[2]);
            }
        }
    }

    // epilogue
    float inv0 = 1.0f / l_run[0], inv1 = 1.0f / l_run[1];
#pragma unroll
    for (int nt = 0; nt < 4; nt++) {
        unsigned hi, lo;
        split2(acc_o[nt][0] * inv0, acc_o[nt][1] * inv0, hi, lo);
        size_t idx0 = (size_t)(b * N_ + iw + r) * CP + h * 16 + nt * 4 + c;
        g_att_hi[idx0] = hi; g_att_lo[idx0] = lo;
        split2(acc_o[nt][2] * inv1, acc_o[nt][3] * inv1, hi, lo);
        size_t idx1 = (size_t)(b * N_ + iw + r + 8) * CP + h * 16 + nt * 4 + c;
        g_att_hi[idx1] = hi; g_att_lo[idx1] = lo;
    }
}

// ---------------------------------------------------------------------------
extern "C" void kernel_launch(void* const* d_in, const int* in_sizes, int n_in,
                              void* d_out, int out_size) {
    const float* x     = (const float*)d_in[0];
    const float* W_qkv = (const float*)d_in[1];
    const float* W_prj = (const float*)d_in[2];
    const float* b_prj = (const float*)d_in[3];
    float* out = (float*)d_out;
    (void)in_sizes; (void)n_in; (void)out_size;

    dim3 gt(C_ / 32, N_ / 32, B_);           // 12 x 32 x 8
    split_x<<<gt, 256>>>(x);

    split_w<<<(O3 * CP + C_ * CP + 255) / 256, 256>>>(W_qkv, W_prj);

    dim3 g1(O3 / 64, N_ / 128, B_);          // 18 x 8 x 8
    gemm_bf16<0><<<g1, 256>>>(nullptr, nullptr);

    dim3 g2(N_ / 128, B_ * NH);              // 8 x 96
    attn_bf16<<<g2, 256>>>();

    dim3 g3(C_ / 64, N_ / 128, B_);          // 6 x 8 x 8
    gemm_bf16<1><<<g3, 256>>>(b_prj, out);
}

// round 5
// speedup vs baseline: 3.0849x; 1.1404x over previous
#include <cuda_runtime.h>
#include <cuda_bf16.h>
#include <math.h>

#define B_    8
#define NH    12
#define N_    1024
#define C_    384
#define CP    192       // C/2 (16-bit pairs per row)
#define O3    1152
#define O3P   576       // O3/2
#define SCALE 0.17677669529663687f
#define QSC   (0.17677669529663687f * 1.4426950408889634f)   // SCALE*log2(e)

// ---------------- scratch (16-bit-pair packed as u32) ----------------
// qkv columns [0,384): Q (bf16 pairs, pre-scaled by QSC)
// qkv columns [384,768): K (bf16 pairs)
// qkv columns [768,1152): V (fp16 pairs)
static __device__ unsigned g_xT_hi[B_ * N_ * CP];
static __device__ unsigned g_xT_lo[B_ * N_ * CP];
static __device__ unsigned g_wq_hi[O3 * CP];
static __device__ unsigned g_wq_lo[O3 * CP];
static __device__ unsigned g_wp_hi[C_ * CP];
static __device__ unsigned g_wp_lo[C_ * CP];
static __device__ unsigned g_qkv_hi[B_ * N_ * O3P];
static __device__ unsigned g_qkv_lo[B_ * N_ * O3P];
static __device__ unsigned g_att_hi[B_ * N_ * CP];
static __device__ unsigned g_att_lo[B_ * N_ * CP];

__device__ __forceinline__ void split2(float f0, float f1, unsigned& hi, unsigned& lo) {
    unsigned h, l;
    asm("cvt.rn.bf16x2.f32 %0, %1, %2;" : "=r"(h) : "f"(f1), "f"(f0));
    float h0 = __uint_as_float(h << 16);
    float h1 = __uint_as_float(h & 0xffff0000u);
    float r0 = f0 - h0, r1 = f1 - h1;
    asm("cvt.rn.bf16x2.f32 %0, %1, %2;" : "=r"(l) : "f"(r1), "f"(r0));
    hi = h; lo = l;
}

// fp16 variant (for V): hi = rn(f), lo = rn(f - hi)
__device__ __forceinline__ void split2h(float f0, float f1, unsigned& hi, unsigned& lo) {
    unsigned h, l;
    asm("cvt.rn.f16x2.f32 %0, %1, %2;" : "=r"(h) : "f"(f1), "f"(f0));
    float h0, h1;
    asm("{.reg .f16 a,b;\n mov.b32 {a,b}, %2;\n cvt.f32.f16 %0, a;\n cvt.f32.f16 %1, b;}"
        : "=f"(h0), "=f"(h1) : "r"(h));
    float r0 = f0 - h0, r1 = f1 - h1;
    asm("cvt.rn.f16x2.f32 %0, %1, %2;" : "=r"(l) : "f"(r1), "f"(r0));
    hi = h; lo = l;
}

__device__ __forceinline__ void mma16816(float* d, const unsigned* a, const unsigned* b) {
    asm volatile(
        "mma.sync.aligned.m16n8k16.row.col.f32.bf16.bf16.f32 "
        "{%0,%1,%2,%3}, {%4,%5,%6,%7}, {%8,%9}, {%0,%1,%2,%3};"
        : "+f"(d[0]), "+f"(d[1]), "+f"(d[2]), "+f"(d[3])
        : "r"(a[0]), "r"(a[1]), "r"(a[2]), "r"(a[3]), "r"(b[0]), "r"(b[1]));
}

__device__ __forceinline__ void mma16816h(float* d, const unsigned* a, const unsigned* b) {
    asm volatile(
        "mma.sync.aligned.m16n8k16.row.col.f32.f16.f16.f32 "
        "{%0,%1,%2,%3}, {%4,%5,%6,%7}, {%8,%9}, {%0,%1,%2,%3};"
        : "+f"(d[0]), "+f"(d[1]), "+f"(d[2]), "+f"(d[3])
        : "r"(a[0]), "r"(a[1]), "r"(a[2]), "r"(a[3]), "r"(b[0]), "r"(b[1]));
}

__device__ __forceinline__ float ex2(float x) {
    float y; asm("ex2.approx.ftz.f32 %0, %1;" : "=f"(y) : "f"(x)); return y;
}

__device__ __forceinline__ unsigned smem_u32p(const void* p) {
    return (unsigned)__cvta_generic_to_shared(p);
}

__device__ __forceinline__ void ldsm_x4(unsigned& r0, unsigned& r1,
                                        unsigned& r2, unsigned& r3, unsigned addr) {
    asm volatile("ldmatrix.sync.aligned.m8n8.x4.shared.b16 {%0,%1,%2,%3}, [%4];"
                 : "=r"(r0), "=r"(r1), "=r"(r2), "=r"(r3) : "r"(addr));
}

__device__ __forceinline__ void ldsm_x4_t(unsigned& r0, unsigned& r1,
                                          unsigned& r2, unsigned& r3, unsigned addr) {
    asm volatile("ldmatrix.sync.aligned.m8n8.x4.trans.shared.b16 {%0,%1,%2,%3}, [%4];"
                 : "=r"(r0), "=r"(r1), "=r"(r2), "=r"(r3) : "r"(addr));
}

__device__ __forceinline__ void cp16(unsigned dst, const void* src) {
    asm volatile("cp.async.cg.shared.global [%0], [%1], 16;" :: "r"(dst), "l"(src));
}
__device__ __forceinline__ void cp_commit() {
    asm volatile("cp.async.commit_group;" ::: "memory");
}
__device__ __forceinline__ void cp_wait0() {
    asm volatile("cp.async.wait_group 0;" ::: "memory");
}

// ---------------- pre-kernel 1: transpose + split x -> xT ----------------
__global__ __launch_bounds__(256) void split_x(const float* __restrict__ x) {
    __shared__ float t[32][33];
    const int k0 = blockIdx.x * 32, m0 = blockIdx.y * 32, b = blockIdx.z;
    const int tx = threadIdx.x & 31, ty = threadIdx.x >> 5;
    const float* xb = x + ((size_t)b * C_ + k0) * N_ + m0;
#pragma unroll
    for (int q = 0; q < 4; q++) t[ty + q * 8][tx] = xb[(size_t)(ty + q * 8) * N_ + tx];
    __syncthreads();
    for (int it = threadIdx.x; it < 512; it += 256) {
        int mp = it >> 4, kp = it & 15;
        unsigned hi, lo;
        split2(t[kp * 2][mp], t[kp * 2 + 1][mp], hi, lo);
        size_t idx = ((size_t)b * N_ + m0 + mp) * CP + (k0 >> 1) + kp;
        g_xT_hi[idx] = hi; g_xT_lo[idx] = lo;
    }
}

// ---------------- pre-kernel 2: split weights ----------------
__global__ __launch_bounds__(256) void split_w(const float* __restrict__ wq,
                                               const float* __restrict__ wp) {
    const int NQ = O3 * CP, NP = C_ * CP;
    int i = blockIdx.x * 256 + threadIdx.x;
    if (i < NQ) {
        float2 f = *(const float2*)(wq + 2 * (size_t)i);
        unsigned hi, lo; split2(f.x, f.y, hi, lo);
        g_wq_hi[i] = hi; g_wq_lo[i] = lo;
    } else if (i < NQ + NP) {
        int j = i - NQ;
        float2 f = *(const float2*)(wp + 2 * (size_t)j);
        unsigned hi, lo; split2(f.x, f.y, hi, lo);
        g_wp_hi[j] = hi; g_wp_lo[j] = lo;
    }
}

// ---------------- GEMM, double-buffered cp.async + LDSM ----------------
template <int EPI>
__global__ __launch_bounds__(256) void gemm_bf16(const float* __restrict__ bias,
                                                 float* __restrict__ out) {
    __shared__ unsigned As_h[2][2560], As_l[2][2560];   // 128 x 20
    __shared__ unsigned Bs_h[2][1280], Bs_l[2][1280];   // 64 x 20

    const unsigned* Ah = EPI ? g_att_hi : g_xT_hi;
    const unsigned* Al = EPI ? g_att_lo : g_xT_lo;
    const unsigned* Bh = EPI ? g_wp_hi  : g_wq_hi;
    const unsigned* Bl = EPI ? g_wp_lo  : g_wq_lo;

    const int b = blockIdx.z;
    const int m0 = blockIdx.y * 128, n0 = blockIdx.x * 64;
    const int tid = threadIdx.x, lane = tid & 31, wid = tid >> 5;
    const int wm = (wid >> 1) * 32, wn = (wid & 1) * 32;
    const int r = lane >> 2, c = lane & 3;

    float acc[2][4][4] = {};

    const int arow = tid >> 1, ahalf = tid & 1;
    const int brow = tid >> 2, bq = tid & 3;
    const unsigned* agp = Ah + ((size_t)(b * N_ + m0 + arow)) * CP + ahalf * 8;
    const unsigned* agl = Al + ((size_t)(b * N_ + m0 + arow)) * CP + ahalf * 8;
    const unsigned* bgp = Bh + (size_t)(n0 + brow) * CP + bq * 4;
    const unsigned* bgl = Bl + (size_t)(n0 + brow) * CP + bq * 4;

    const unsigned dAh0 = smem_u32p(&As_h[0][arow * 20 + ahalf * 8]);
    const unsigned dAl0 = smem_u32p(&As_l[0][arow * 20 + ahalf * 8]);
    const unsigned dBh0 = smem_u32p(&Bs_h[0][brow * 20 + bq * 4]);
    const unsigned dBl0 = smem_u32p(&Bs_l[0][brow * 20 + bq * 4]);

    const unsigned offA = ((wm + (lane & 15)) * 20 + (lane >> 4) * 4) * 4;
    const unsigned baseAh = smem_u32p(As_h) + offA;
    const unsigned baseAl = smem_u32p(As_l) + offA;
    const unsigned offB = ((wn + (lane & 7) + ((lane >> 4) << 3)) * 20 +
                           ((lane >> 3) & 1) * 4) * 4;
    const unsigned baseBh = smem_u32p(Bs_h) + offB;
    const unsigned baseBl = smem_u32p(Bs_l) + offB;

#define GEMM_STAGE(kc, sel)                                             \
    do {                                                                \
        unsigned so = (sel) * 10240, sob = (sel) * 5120;                \
        cp16(dAh0 + so,      agp + (kc) * 16);                          \
        cp16(dAh0 + so + 16, agp + (kc) * 16 + 4);                      \
        cp16(dAl0 + so,      agl + (kc) * 16);                          \
        cp16(dAl0 + so + 16, agl + (kc) * 16 + 4);                      \
        cp16(dBh0 + sob,     bgp + (kc) * 16);                          \
        cp16(dBl0 + sob,     bgl + (kc) * 16);                          \
    } while (0)

    GEMM_STAGE(0, 0);
    cp_commit();

    for (int kc = 0; kc < 12; kc++) {
        const int sel = kc & 1;
        cp_wait0();
        __syncthreads();
        if (kc < 11) { GEMM_STAGE(kc + 1, sel ^ 1); cp_commit(); }

        const unsigned sa = sel * 10240, sb = sel * 5120;
#pragma unroll
        for (int ks = 0; ks < 2; ks++) {
            unsigned ah[2][4], al[2][4];
#pragma unroll
            for (int mt = 0; mt < 2; mt++) {
                ldsm_x4(ah[mt][0], ah[mt][1], ah[mt][2], ah[mt][3],
                        baseAh + sa + mt * 1280 + ks * 32);
                ldsm_x4(al[mt][0], al[mt][1], al[mt][2], al[mt][3],
                        baseAl + sa + mt * 1280 + ks * 32);
            }
#pragma unroll
            for (int tp = 0; tp < 2; tp++) {
                unsigned bh[4], bl[4];
                ldsm_x4(bh[0], bh[1], bh[2], bh[3], baseBh + sb + tp * 1280 + ks * 32);
                ldsm_x4(bl[0], bl[1], bl[2], bl[3], baseBl + sb + tp * 1280 + ks * 32);
#pragma unroll
                for (int mt = 0; mt < 2; mt++) {
                    mma16816(acc[mt][2 * tp],     ah[mt], &bh[0]);
                    mma16816(acc[mt][2 * tp],     al[mt], &bh[0]);
                    mma16816(acc[mt][2 * tp],     ah[mt], &bl[0]);
                    mma16816(acc[mt][2 * tp + 1], ah[mt], &bh[2]);
                    mma16816(acc[mt][2 * tp + 1], al[mt], &bh[2]);
                    mma16816(acc[mt][2 * tp + 1], ah[mt], &bl[2]);
                }
            }
        }
    }

    if (EPI == 0) {
        // Q columns pre-scaled by SCALE*log2e; V columns stored as fp16 pairs
        const float qs = (n0 < 384) ? QSC : 1.0f;
        const bool isV = (n0 >= 768);
#pragma unroll
        for (int mt = 0; mt < 2; mt++)
#pragma unroll
            for (int nt = 0; nt < 4; nt++) {
                int m = m0 + wm + mt * 16 + r;
                int colp = (n0 >> 1) + (wn >> 1) + nt * 4 + c;
                float a0 = acc[mt][nt][0] * qs, a1 = acc[mt][nt][1] * qs;
                float a2 = acc[mt][nt][2] * qs, a3 = acc[mt][nt][3] * qs;
                unsigned hi, lo;
                if (isV) split2h(a0, a1, hi, lo); else split2(a0, a1, hi, lo);
                g_qkv_hi[(size_t)(b * N_ + m) * O3P + colp] = hi;
                g_qkv_lo[(size_t)(b * N_ + m) * O3P + colp] = lo;
                if (isV) split2h(a2, a3, hi, lo); else split2(a2, a3, hi, lo);
                g_qkv_hi[(size_t)(b * N_ + m + 8) * O3P + colp] = hi;
                g_qkv_lo[(size_t)(b * N_ + m + 8) * O3P + colp] = lo;
            }
    } else {
#pragma unroll
        for (int mt = 0; mt < 2; mt++)
#pragma unroll
            for (int nt = 0; nt < 4; nt++)
#pragma unroll
                for (int q = 0; q < 4; q++) {
                    int o = n0 + wn + nt * 8 + 2 * c + (q & 1);
                    int m = m0 + wm + mt * 16 + r + ((q >> 1) * 8);
                    out[((size_t)b * C_ + o) * N_ + m] = acc[mt][nt][q] + bias[o];
                }
    }
}

// ---------------- flash attention ----------------
// Q pre-scaled (log2 domain), K bf16 3-term, PV fp16 2-term.
__global__ __launch_bounds__(256) void attn_bf16() {
    __shared__ unsigned Ks_h[2][1280], Ks_l[2][1280];   // [j=64][20] bf16 pairs
    __shared__ unsigned Vs_h[2][1280], Vs_l[2][1280];   // [j=64][20] fp16 pairs

    const int tid = threadIdx.x, lane = tid & 31, wid = tid >> 5;
    const int bh = blockIdx.y, b = bh / NH, h = bh % NH;
    const int i0 = blockIdx.x * 128;
    const int iw = i0 + wid * 16;
    const int r = lane >> 2, c = lane & 3;

    // Q fragments (global, once)
    unsigned qh[2][4], ql[2][4];
    {
        const unsigned* qb_h = g_qkv_hi + (size_t)(b * N_ + iw) * O3P + h * 16;
        const unsigned* qb_l = g_qkv_lo + (size_t)(b * N_ + iw) * O3P + h * 16;
#pragma unroll
        for (int ks = 0; ks < 2; ks++) {
            qh[ks][0] = qb_h[(size_t)r * O3P + ks * 8 + c];
            qh[ks][1] = qb_h[(size_t)(r + 8) * O3P + ks * 8 + c];
            qh[ks][2] = qb_h[(size_t)r * O3P + ks * 8 + 4 + c];
            qh[ks][3] = qb_h[(size_t)(r + 8) * O3P + ks * 8 + 4 + c];
            ql[ks][0] = qb_l[(size_t)r * O3P + ks * 8 + c];
            ql[ks][1] = qb_l[(size_t)(r + 8) * O3P + ks * 8 + c];
            ql[ks][2] = qb_l[(size_t)r * O3P + ks * 8 + 4 + c];
            ql[ks][3] = qb_l[(size_t)(r + 8) * O3P + ks * 8 + 4 + c];
        }
    }

    const int srow = tid >> 2, sq = tid & 3;
    const size_t srcK = (size_t)(b * N_ + srow) * O3P + 192 + h * 16 + sq * 4;
    const size_t srcV = (size_t)(b * N_ + srow) * O3P + 384 + h * 16 + sq * 4;
    const unsigned dK = smem_u32p(&Ks_h[0][srow * 20 + sq * 4]);
    const unsigned dKl = smem_u32p(&Ks_l[0][srow * 20 + sq * 4]);
    const unsigned dV = smem_u32p(&Vs_h[0][srow * 20 + sq * 4]);
    const unsigned dVl = smem_u32p(&Vs_l[0][srow * 20 + sq * 4]);

#define ATTN_STAGE(jt, sel)                                            \
    do {                                                               \
        size_t ro = (size_t)(jt) * 64 * O3P;                           \
        unsigned so = (sel) * 5120;                                    \
        cp16(dK  + so, g_qkv_hi + srcK + ro);                          \
        cp16(dKl + so, g_qkv_lo + srcK + ro);                          \
        cp16(dV  + so, g_qkv_hi + srcV + ro);                          \
        cp16(dVl + so, g_qkv_lo + srcV + ro);                          \
    } while (0)

    const unsigned offK = (((lane & 7) + ((lane >> 4) << 3)) * 20 +
                           ((lane >> 3) & 1) * 4) * 4;
    const unsigned baseKh = smem_u32p(Ks_h) + offK;
    const unsigned baseKl = smem_u32p(Ks_l) + offK;
    const unsigned offV = (((lane >> 3) & 1) * 8 + (lane & 7)) * 80 +
                          (lane >> 4) * 16;
    const unsigned baseVh = smem_u32p(Vs_h) + offV;
    const unsigned baseVl = smem_u32p(Vs_l) + offV;

    float m_run[2] = {-1e30f, -1e30f}, l_run[2] = {0.f, 0.f};
    float acc_o[4][4] = {};

    ATTN_STAGE(0, 0);
    cp_commit();

    for (int jt = 0; jt < 16; jt++) {
        const int sel = jt & 1;
        cp_wait0();
        __syncthreads();
        if (jt < 15) { ATTN_STAGE(jt + 1, sel ^ 1); cp_commit(); }

        const unsigned so = sel * 5120;

        // S = Q K^T  (already in log2 units; Q pre-scaled)
        float s[8][4] = {};
#pragma unroll
        for (int ks = 0; ks < 2; ks++)
#pragma unroll
            for (int tp = 0; tp < 4; tp++) {
                unsigned kh[4], kl[4];
                ldsm_x4(kh[0], kh[1], kh[2], kh[3], baseKh + so + tp * 1280 + ks * 32);
                ldsm_x4(kl[0], kl[1], kl[2], kl[3], baseKl + so + tp * 1280 + ks * 32);
                mma16816(s[2 * tp],     qh[ks], &kh[0]);
                mma16816(s[2 * tp],     ql[ks], &kh[0]);
                mma16816(s[2 * tp],     qh[ks], &kl[0]);
                mma16816(s[2 * tp + 1], qh[ks], &kh[2]);
                mma16816(s[2 * tp + 1], ql[ks], &kh[2]);
                mma16816(s[2 * tp + 1], qh[ks], &kl[2]);
            }

        // online softmax in log2 domain
        float mx0 = m_run[0], mx1 = m_run[1];
#pragma unroll
        for (int nt = 0; nt < 8; nt++) {
            mx0 = fmaxf(mx0, fmaxf(s[nt][0], s[nt][1]));
            mx1 = fmaxf(mx1, fmaxf(s[nt][2], s[nt][3]));
        }
        mx0 = fmaxf(mx0, __shfl_xor_sync(0xffffffffu, mx0, 1));
        mx0 = fmaxf(mx0, __shfl_xor_sync(0xffffffffu, mx0, 2));
        mx1 = fmaxf(mx1, __shfl_xor_sync(0xffffffffu, mx1, 1));
        mx1 = fmaxf(mx1, __shfl_xor_sync(0xffffffffu, mx1, 2));
        float corr0 = ex2(m_run[0] - mx0);
        float corr1 = ex2(m_run[1] - mx1);
        float rs0 = 0.f, rs1 = 0.f;
#pragma unroll
        for (int nt = 0; nt < 8; nt++) {
            s[nt][0] = ex2(s[nt][0] - mx0);
            s[nt][1] = ex2(s[nt][1] - mx0);
            s[nt][2] = ex2(s[nt][2] - mx1);
            s[nt][3] = ex2(s[nt][3] - mx1);
            rs0 += s[nt][0] + s[nt][1];
            rs1 += s[nt][2] + s[nt][3];
        }
        rs0 += __shfl_xor_sync(0xffffffffu, rs0, 1);
        rs0 += __shfl_xor_sync(0xffffffffu, rs0, 2);
        rs1 += __shfl_xor_sync(0xffffffffu, rs1, 1);
        rs1 += __shfl_xor_sync(0xffffffffu, rs1, 2);
        l_run[0] = l_run[0] * corr0 + rs0;
        l_run[1] = l_run[1] * corr1 + rs1;
        m_run[0] = mx0; m_run[1] = mx1;
#pragma unroll
        for (int nt = 0; nt < 4; nt++) {
            acc_o[nt][0] *= corr0; acc_o[nt][1] *= corr0;
            acc_o[nt][2] *= corr1; acc_o[nt][3] *= corr1;
        }

        // O += P V  (P single fp16; V fp16 hi+lo via trans LDSM)
#pragma unroll
        for (int kk = 0; kk < 4; kk++) {
            unsigned ph[4];
            asm("cvt.rn.f16x2.f32 %0, %1, %2;" : "=r"(ph[0])
                : "f"(s[2 * kk][1]), "f"(s[2 * kk][0]));
            asm("cvt.rn.f16x2.f32 %0, %1, %2;" : "=r"(ph[1])
                : "f"(s[2 * kk][3]), "f"(s[2 * kk][2]));
            asm("cvt.rn.f16x2.f32 %0, %1, %2;" : "=r"(ph[2])
                : "f"(s[2 * kk + 1][1]), "f"(s[2 * kk + 1][0]));
            asm("cvt.rn.f16x2.f32 %0, %1, %2;" : "=r"(ph[3])
                : "f"(s[2 * kk + 1][3]), "f"(s[2 * kk + 1][2]));
#pragma unroll
            for (int tp = 0; tp < 2; tp++) {
                unsigned vh[4], vl[4];
                ldsm_x4_t(vh[0], vh[1], vh[2], vh[3],
                          baseVh + so + kk * 1280 + tp * 32);
                ldsm_x4_t(vl[0], vl[1], vl[2], vl[3],
                          baseVl + so + kk * 1280 + tp * 32);
                mma16816h(acc_o[2 * tp],     ph, &vh[0]);
                mma16816h(acc_o[2 * tp],     ph, &vl[0]);
                mma16816h(acc_o[2 * tp + 1], ph, &vh[2]);
                mma16816h(acc_o[2 * tp + 1], ph, &vl[2]);
            }
        }
    }

    // epilogue: normalize, bf16 split (for proj GEMM), store att
    float inv0 = 1.0f / l_run[0], inv1 = 1.0f / l_run[1];
#pragma unroll
    for (int nt = 0; nt < 4; nt++) {
        unsigned hi, lo;
        split2(acc_o[nt][0] * inv0, acc_o[nt][1] * inv0, hi, lo);
        size_t idx0 = (size_t)(b * N_ + iw + r) * CP + h * 16 + nt * 4 + c;
        g_att_hi[idx0] = hi; g_att_lo[idx0] = lo;
        split2(acc_o[nt][2] * inv1, acc_o[nt][3] * inv1, hi, lo);
        size_t idx1 = (size_t)(b * N_ + iw + r + 8) * CP + h * 16 + nt * 4 + c;
        g_att_hi[idx1] = hi; g_att_lo[idx1] = lo;
    }
}

// ---------------------------------------------------------------------------
extern "C" void kernel_launch(void* const* d_in, const int* in_sizes, int n_in,
                              void* d_out, int out_size) {
    const float* x     = (const float*)d_in[0];
    const float* W_qkv = (const float*)d_in[1];
    const float* W_prj = (const float*)d_in[2];
    const float* b_prj = (const float*)d_in[3];
    float* out = (float*)d_out;
    (void)in_sizes; (void)n_in; (void)out_size;

    dim3 gt(C_ / 32, N_ / 32, B_);           // 12 x 32 x 8
    split_x<<<gt, 256>>>(x);

    split_w<<<(O3 * CP + C_ * CP + 255) / 256, 256>>>(W_qkv, W_prj);

    dim3 g1(O3 / 64, N_ / 128, B_);          // 18 x 8 x 8
    gemm_bf16<0><<<g1, 256>>>(nullptr, nullptr);

    dim3 g2(N_ / 128, B_ * NH);              // 8 x 96
    attn_bf16<<<g2, 256>>>();

    dim3 g3(C_ / 64, N_ / 128, B_);          // 6 x 8 x 8
    gemm_bf16<1><<<g3, 256>>>(b_prj, out);
}

// round 8
// speedup vs baseline: 3.3687x; 1.0920x over previous
#include <cuda_runtime.h>
#include <cuda_bf16.h>
#include <math.h>

#define B_    8
#define NH    12
#define N_    1024
#define C_    384
#define CP    192       // C/2 (16-bit pairs per row)
#define O3    1152
#define O3P   576       // O3/2
#define SCALE 0.17677669529663687f
#define QSC   (0.17677669529663687f * 1.4426950408889634f)   // SCALE*log2(e)

// ---------------- scratch (16-bit-pair packed as u32) ----------------
// qkv cols [0,384): Q bf16 (pre-scaled by QSC); [384,768): K bf16; [768,1152): V fp16
static __device__ unsigned g_xT_hi[B_ * N_ * CP];
static __device__ unsigned g_xT_lo[B_ * N_ * CP];
static __device__ unsigned g_wq_hi[O3 * CP];
static __device__ unsigned g_wq_lo[O3 * CP];
static __device__ unsigned g_wp_hi[C_ * CP];
static __device__ unsigned g_wp_lo[C_ * CP];
static __device__ unsigned g_qkv_hi[B_ * N_ * O3P];
static __device__ unsigned g_qkv_lo[B_ * N_ * O3P];
static __device__ unsigned g_att_hi[B_ * N_ * CP];
static __device__ unsigned g_att_lo[B_ * N_ * CP];

__device__ __forceinline__ void split2(float f0, float f1, unsigned& hi, unsigned& lo) {
    unsigned h, l;
    asm("cvt.rn.bf16x2.f32 %0, %1, %2;" : "=r"(h) : "f"(f1), "f"(f0));
    float h0 = __uint_as_float(h << 16);
    float h1 = __uint_as_float(h & 0xffff0000u);
    float r0 = f0 - h0, r1 = f1 - h1;
    asm("cvt.rn.bf16x2.f32 %0, %1, %2;" : "=r"(l) : "f"(r1), "f"(r0));
    hi = h; lo = l;
}

__device__ __forceinline__ void split2h(float f0, float f1, unsigned& hi, unsigned& lo) {
    unsigned h, l;
    asm("cvt.rn.f16x2.f32 %0, %1, %2;" : "=r"(h) : "f"(f1), "f"(f0));
    float h0, h1;
    asm("{.reg .f16 a,b;\n mov.b32 {a,b}, %2;\n cvt.f32.f16 %0, a;\n cvt.f32.f16 %1, b;}"
        : "=f"(h0), "=f"(h1) : "r"(h));
    float r0 = f0 - h0, r1 = f1 - h1;
    asm("cvt.rn.f16x2.f32 %0, %1, %2;" : "=r"(l) : "f"(r1), "f"(r0));
    hi = h; lo = l;
}

__device__ __forceinline__ void mma16816(float* d, const unsigned* a, const unsigned* b) {
    asm volatile(
        "mma.sync.aligned.m16n8k16.row.col.f32.bf16.bf16.f32 "
        "{%0,%1,%2,%3}, {%4,%5,%6,%7}, {%8,%9}, {%0,%1,%2,%3};"
        : "+f"(d[0]), "+f"(d[1]), "+f"(d[2]), "+f"(d[3])
        : "r"(a[0]), "r"(a[1]), "r"(a[2]), "r"(a[3]), "r"(b[0]), "r"(b[1]));
}

__device__ __forceinline__ void mma16816h(float* d, const unsigned* a, const unsigned* b) {
    asm volatile(
        "mma.sync.aligned.m16n8k16.row.col.f32.f16.f16.f32 "
        "{%0,%1,%2,%3}, {%4,%5,%6,%7}, {%8,%9}, {%0,%1,%2,%3};"
        : "+f"(d[0]), "+f"(d[1]), "+f"(d[2]), "+f"(d[3])
        : "r"(a[0]), "r"(a[1]), "r"(a[2]), "r"(a[3]), "r"(b[0]), "r"(b[1]));
}

__device__ __forceinline__ float ex2(float x) {
    float y; asm("ex2.approx.ftz.f32 %0, %1;" : "=f"(y) : "f"(x)); return y;
}

__device__ __forceinline__ unsigned smem_u32p(const void* p) {
    return (unsigned)__cvta_generic_to_shared(p);
}

__device__ __forceinline__ void ldsm_x4(unsigned& r0, unsigned& r1,
                                        unsigned& r2, unsigned& r3, unsigned addr) {
    asm volatile("ldmatrix.sync.aligned.m8n8.x4.shared.b16 {%0,%1,%2,%3}, [%4];"
                 : "=r"(r0), "=r"(r1), "=r"(r2), "=r"(r3) : "r"(addr));
}

__device__ __forceinline__ void ldsm_x4_t(unsigned& r0, unsigned& r1,
                                          unsigned& r2, unsigned& r3, unsigned addr) {
    asm volatile("ldmatrix.sync.aligned.m8n8.x4.trans.shared.b16 {%0,%1,%2,%3}, [%4];"
                 : "=r"(r0), "=r"(r1), "=r"(r2), "=r"(r3) : "r"(addr));
}

__device__ __forceinline__ void cp16(unsigned dst, const void* src) {
    asm volatile("cp.async.cg.shared.global [%0], [%1], 16;" :: "r"(dst), "l"(src));
}
__device__ __forceinline__ void cp_commit() {
    asm volatile("cp.async.commit_group;" ::: "memory");
}
__device__ __forceinline__ void cp_wait0() {
    asm volatile("cp.async.wait_group 0;" ::: "memory");
}

// ---------------- pre-kernel 1: transpose + split x -> xT ----------------
__global__ __launch_bounds__(256) void split_x(const float* __restrict__ x) {
    __shared__ float t[32][33];
    const int k0 = blockIdx.x * 32, m0 = blockIdx.y * 32, b = blockIdx.z;
    const int tx = threadIdx.x & 31, ty = threadIdx.x >> 5;
    const float* xb = x + ((size_t)b * C_ + k0) * N_ + m0;
#pragma unroll
    for (int q = 0; q < 4; q++) t[ty + q * 8][tx] = xb[(size_t)(ty + q * 8) * N_ + tx];
    __syncthreads();
    for (int it = threadIdx.x; it < 512; it += 256) {
        int mp = it >> 4, kp = it & 15;
        unsigned hi, lo;
        split2(t[kp * 2][mp], t[kp * 2 + 1][mp], hi, lo);
        size_t idx = ((size_t)b * N_ + m0 + mp) * CP + (k0 >> 1) + kp;
        g_xT_hi[idx] = hi; g_xT_lo[idx] = lo;
    }
}

// ---------------- pre-kernel 2: split weights ----------------
__global__ __launch_bounds__(256) void split_w(const float* __restrict__ wq,
                                               const float* __restrict__ wp) {
    const int NQ = O3 * CP, NP = C_ * CP;
    int i = blockIdx.x * 256 + threadIdx.x;
    if (i < NQ) {
        float2 f = *(const float2*)(wq + 2 * (size_t)i);
        unsigned hi, lo; split2(f.x, f.y, hi, lo);
        g_wq_hi[i] = hi; g_wq_lo[i] = lo;
    } else if (i < NQ + NP) {
        int j = i - NQ;
        float2 f = *(const float2*)(wp + 2 * (size_t)j);
        unsigned hi, lo; split2(f.x, f.y, hi, lo);
        g_wp_hi[j] = hi; g_wp_lo[j] = lo;
    }
}

// ---------------- GEMM: 128m x 128n block, 512 threads (16 warps 4x4) -----
// C[m][n] = sum_k A[m][k]*B[n][k], bf16 3-term split, dbl-buffered cp.async.
// dynamic smem: Ah[2]@0, Al[2]@20480, Bh[2]@40960, Bl[2]@61440 (10240B each buf)
#define GSMEM_TOTAL 81920
template <int EPI>
__global__ __launch_bounds__(512) void gemm_bf16(const float* __restrict__ bias,
                                                 float* __restrict__ out) {
    extern __shared__ unsigned gsm[];
    const unsigned smb = smem_u32p(gsm);

    const unsigned* Agh = EPI ? g_att_hi : g_xT_hi;
    const unsigned* Agl = EPI ? g_att_lo : g_xT_lo;
    const unsigned* Bgh = EPI ? g_wp_hi  : g_wq_hi;
    const unsigned* Bgl = EPI ? g_wp_lo  : g_wq_lo;

    const int b = blockIdx.z;
    const int m0 = blockIdx.y * 128, n0 = blockIdx.x * 128;
    const int tid = threadIdx.x, lane = tid & 31, wid = tid >> 5;
    const int wm = (wid >> 2) * 32, wn = (wid & 3) * 32;
    const int r = lane >> 2, c = lane & 3;

    float acc[2][4][4] = {};

    // staging: row = tid>>2, quarter = tid&3 -> one cp16 into each array
    const int srow = tid >> 2, sq = tid & 3;
    const unsigned* agp = Agh + (size_t)(b * N_ + m0 + srow) * CP + sq * 4;
    const unsigned* agl = Agl + (size_t)(b * N_ + m0 + srow) * CP + sq * 4;
    const unsigned* bgp = Bgh + (size_t)(n0 + srow) * CP + sq * 4;
    const unsigned* bgl = Bgl + (size_t)(n0 + srow) * CP + sq * 4;
    const unsigned dst0 = smb + (srow * 20 + sq * 4) * 4;   // byte offset in buf

#define GEMM_STAGE(kc, sel)                                             \
    do {                                                                \
        unsigned so = (sel) * 10240;                                    \
        cp16(dst0 + so,         agp + (kc) * 16);                       \
        cp16(dst0 + 20480 + so, agl + (kc) * 16);                       \
        cp16(dst0 + 40960 + so, bgp + (kc) * 16);                       \
        cp16(dst0 + 61440 + so, bgl + (kc) * 16);                       \
    } while (0)

    const unsigned offA = ((wm + (lane & 15)) * 20 + (lane >> 4) * 4) * 4;
    const unsigned baseAh = smb + offA;
    const unsigned baseAl = smb + 20480 + offA;
    const unsigned offB = ((wn + (lane & 7) + ((lane >> 4) << 3)) * 20 +
                           ((lane >> 3) & 1) * 4) * 4;
    const unsigned baseBh = smb + 40960 + offB;
    const unsigned baseBl = smb + 61440 + offB;

    GEMM_STAGE(0, 0);
    cp_commit();

    for (int kc = 0; kc < 12; kc++) {
        const int sel = kc & 1;
        cp_wait0();
        __syncthreads();
        if (kc < 11) { GEMM_STAGE(kc + 1, sel ^ 1); cp_commit(); }

        const unsigned so = sel * 10240;
#pragma unroll
        for (int ks = 0; ks < 2; ks++) {
            unsigned ah[2][4], al[2][4];
#pragma unroll
            for (int mt = 0; mt < 2; mt++) {
                ldsm_x4(ah[mt][0], ah[mt][1], ah[mt][2], ah[mt][3],
                        baseAh + so + mt * 1280 + ks * 32);
                ldsm_x4(al[mt][0], al[mt][1], al[mt][2], al[mt][3],
                        baseAl + so + mt * 1280 + ks * 32);
            }
#pragma unroll
            for (int tp = 0; tp < 2; tp++) {
                unsigned bh[4], bl[4];
                ldsm_x4(bh[0], bh[1], bh[2], bh[3], baseBh + so + tp * 1280 + ks * 32);
                ldsm_x4(bl[0], bl[1], bl[2], bl[3], baseBl + so + tp * 1280 + ks * 32);
#pragma unroll
                for (int mt = 0; mt < 2; mt++) {
                    mma16816(acc[mt][2 * tp],     ah[mt], &bh[0]);
                    mma16816(acc[mt][2 * tp],     al[mt], &bh[0]);
                    mma16816(acc[mt][2 * tp],     ah[mt], &bl[0]);
                    mma16816(acc[mt][2 * tp + 1], ah[mt], &bh[2]);
                    mma16816(acc[mt][2 * tp + 1], al[mt], &bh[2]);
                    mma16816(acc[mt][2 * tp + 1], ah[mt], &bl[2]);
                }
            }
        }
    }

    if (EPI == 0) {
        // n0 is 128-aligned; Q/K/V boundaries (384, 768) are 128-multiples
        const float qs = (n0 < 384) ? QSC : 1.0f;
        const bool isV = (n0 >= 768);
#pragma unroll
        for (int mt = 0; mt < 2; mt++)
#pragma unroll
            for (int nt = 0; nt < 4; nt++) {
                int m = m0 + wm + mt * 16 + r;
                int colp = (n0 >> 1) + (wn >> 1) + nt * 4 + c;
                float a0 = acc[mt][nt][0] * qs, a1 = acc[mt][nt][1] * qs;
                float a2 = acc[mt][nt][2] * qs, a3 = acc[mt][nt][3] * qs;
                unsigned hi, lo;
                if (isV) split2h(a0, a1, hi, lo); else split2(a0, a1, hi, lo);
                g_qkv_hi[(size_t)(b * N_ + m) * O3P + colp] = hi;
                g_qkv_lo[(size_t)(b * N_ + m) * O3P + colp] = lo;
                if (isV) split2h(a2, a3, hi, lo); else split2(a2, a3, hi, lo);
                g_qkv_hi[(size_t)(b * N_ + m + 8) * O3P + colp] = hi;
                g_qkv_lo[(size_t)(b * N_ + m + 8) * O3P + colp] = lo;
            }
    } else {
#pragma unroll
        for (int mt = 0; mt < 2; mt++)
#pragma unroll
            for (int nt = 0; nt < 4; nt++)
#pragma unroll
                for (int q = 0; q < 4; q++) {
                    int o = n0 + wn + nt * 8 + 2 * c + (q & 1);
                    int m = m0 + wm + mt * 16 + r + ((q >> 1) * 8);
                    out[((size_t)b * C_ + o) * N_ + m] = acc[mt][nt][q] + bias[o];
                }
    }
}

// ---------------- flash attention ----------------
// Q pre-scaled (log2 domain), K bf16 3-term QK, PV fp16 (P fp16, V hi-only).
__global__ __launch_bounds__(256) void attn_bf16() {
    __shared__ unsigned Ks_h[2][1280], Ks_l[2][1280];   // [j=64][20] bf16 pairs
    __shared__ unsigned Vs_h[2][1280];                  // [j=64][20] fp16 pairs

    const int tid = threadIdx.x, lane = tid & 31, wid = tid >> 5;
    const int bh = blockIdx.y, b = bh / NH, h = bh % NH;
    const int i0 = blockIdx.x * 128;
    const int iw = i0 + wid * 16;
    const int r = lane >> 2, c = lane & 3;

    unsigned qh[2][4], ql[2][4];
    {
        const unsigned* qb_h = g_qkv_hi + (size_t)(b * N_ + iw) * O3P + h * 16;
        const unsigned* qb_l = g_qkv_lo + (size_t)(b * N_ + iw) * O3P + h * 16;
#pragma unroll
        for (int ks = 0; ks < 2; ks++) {
            qh[ks][0] = qb_h[(size_t)r * O3P + ks * 8 + c];
            qh[ks][1] = qb_h[(size_t)(r + 8) * O3P + ks * 8 + c];
            qh[ks][2] = qb_h[(size_t)r * O3P + ks * 8 + 4 + c];
            qh[ks][3] = qb_h[(size_t)(r + 8) * O3P + ks * 8 + 4 + c];
            ql[ks][0] = qb_l[(size_t)r * O3P + ks * 8 + c];
            ql[ks][1] = qb_l[(size_t)(r + 8) * O3P + ks * 8 + c];
            ql[ks][2] = qb_l[(size_t)r * O3P + ks * 8 + 4 + c];
            ql[ks][3] = qb_l[(size_t)(r + 8) * O3P + ks * 8 + 4 + c];
        }
    }

    const int srow = tid >> 2, sq = tid & 3;
    const size_t srcK = (size_t)(b * N_ + srow) * O3P + 192 + h * 16 + sq * 4;
    const size_t srcV = (size_t)(b * N_ + srow) * O3P + 384 + h * 16 + sq * 4;
    const unsigned dK  = smem_u32p(&Ks_h[0][srow * 20 + sq * 4]);
    const unsigned dKl = smem_u32p(&Ks_l[0][srow * 20 + sq * 4]);
    const unsigned dV  = smem_u32p(&Vs_h[0][srow * 20 + sq * 4]);

#define ATTN_STAGE(jt, sel)                                            \
    do {                                                               \
        size_t ro = (size_t)(jt) * 64 * O3P;                           \
        unsigned so = (sel) * 5120;                                    \
        cp16(dK  + so, g_qkv_hi + srcK + ro);                          \
        cp16(dKl + so, g_qkv_lo + srcK + ro);                          \
        cp16(dV  + so, g_qkv_hi + srcV + ro);                          \
    } while (0)

    const unsigned offK = (((lane & 7) + ((lane >> 4) << 3)) * 20 +
                           ((lane >> 3) & 1) * 4) * 4;
    const unsigned baseKh = smem_u32p(Ks_h) + offK;
    const unsigned baseKl = smem_u32p(Ks_l) + offK;
    const unsigned offV = (((lane >> 3) & 1) * 8 + (lane & 7)) * 80 +
                          (lane >> 4) * 16;
    const unsigned baseVh = smem_u32p(Vs_h) + offV;

    float m_run[2] = {-1e30f, -1e30f}, l_run[2] = {0.f, 0.f};
    float acc_o[4][4] = {};

    ATTN_STAGE(0, 0);
    cp_commit();

    for (int jt = 0; jt < 16; jt++) {
        const int sel = jt & 1;
        cp_wait0();
        __syncthreads();
        if (jt < 15) { ATTN_STAGE(jt + 1, sel ^ 1); cp_commit(); }

        const unsigned so = sel * 5120;

        float s[8][4] = {};
#pragma unroll
        for (int ks = 0; ks < 2; ks++)
#pragma unroll
            for (int tp = 0; tp < 4; tp++) {
                unsigned kh[4], kl[4];
                ldsm_x4(kh[0], kh[1], kh[2], kh[3], baseKh + so + tp * 1280 + ks * 32);
                ldsm_x4(kl[0], kl[1], kl[2], kl[3], baseKl + so + tp * 1280 + ks * 32);
                mma16816(s[2 * tp],     qh[ks], &kh[0]);
                mma16816(s[2 * tp],     ql[ks], &kh[0]);
                mma16816(s[2 * tp],     qh[ks], &kl[0]);
                mma16816(s[2 * tp + 1], qh[ks], &kh[2]);
                mma16816(s[2 * tp + 1], ql[ks], &kh[2]);
                mma16816(s[2 * tp + 1], qh[ks], &kl[2]);
            }

        float mx0 = m_run[0], mx1 = m_run[1];
#pragma unroll
        for (int nt = 0; nt < 8; nt++) {
            mx0 = fmaxf(mx0, fmaxf(s[nt][0], s[nt][1]));
            mx1 = fmaxf(mx1, fmaxf(s[nt][2], s[nt][3]));
        }
        mx0 = fmaxf(mx0, __shfl_xor_sync(0xffffffffu, mx0, 1));
        mx0 = fmaxf(mx0, __shfl_xor_sync(0xffffffffu, mx0, 2));
        mx1 = fmaxf(mx1, __shfl_xor_sync(0xffffffffu, mx1, 1));
        mx1 = fmaxf(mx1, __shfl_xor_sync(0xffffffffu, mx1, 2));
        float corr0 = ex2(m_run[0] - mx0);
        float corr1 = ex2(m_run[1] - mx1);
        float rs0 = 0.f, rs1 = 0.f;
#pragma unroll
        for (int nt = 0; nt < 8; nt++) {
            s[nt][0] = ex2(s[nt][0] - mx0);
            s[nt][1] = ex2(s[nt][1] - mx0);
            s[nt][2] = ex2(s[nt][2] - mx1);
            s[nt][3] = ex2(s[nt][3] - mx1);
            rs0 += s[nt][0] + s[nt][1];
            rs1 += s[nt][2] + s[nt][3];
        }
        rs0 += __shfl_xor_sync(0xffffffffu, rs0, 1);
        rs0 += __shfl_xor_sync(0xffffffffu, rs0, 2);
        rs1 += __shfl_xor_sync(0xffffffffu, rs1, 1);
        rs1 += __shfl_xor_sync(0xffffffffu, rs1, 2);
        l_run[0] = l_run[0] * corr0 + rs0;
        l_run[1] = l_run[1] * corr1 + rs1;
        m_run[0] = mx0; m_run[1] = mx1;
#pragma unroll
        for (int nt = 0; nt < 4; nt++) {
            acc_o[nt][0] *= corr0; acc_o[nt][1] *= corr0;
            acc_o[nt][2] *= corr1; acc_o[nt][3] *= corr1;
        }

#pragma unroll
        for (int kk = 0; kk < 4; kk++) {
            unsigned ph[4];
            asm("cvt.rn.f16x2.f32 %0, %1, %2;" : "=r"(ph[0])
                : "f"(s[2 * kk][1]), "f"(s[2 * kk][0]));
            asm("cvt.rn.f16x2.f32 %0, %1, %2;" : "=r"(ph[1])
                : "f"(s[2 * kk][3]), "f"(s[2 * kk][2]));
            asm("cvt.rn.f16x2.f32 %0, %1, %2;" : "=r"(ph[2])
                : "f"(s[2 * kk + 1][1]), "f"(s[2 * kk + 1][0]));
            asm("cvt.rn.f16x2.f32 %0, %1, %2;" : "=r"(ph[3])
                : "f"(s[2 * kk + 1][3]), "f"(s[2 * kk + 1][2]));
#pragma unroll
            for (int tp = 0; tp < 2; tp++) {
                unsigned vh[4];
                ldsm_x4_t(vh[0], vh[1], vh[2], vh[3],
                          baseVh + so + kk * 1280 + tp * 32);
                mma16816h(acc_o[2 * tp],     ph, &vh[0]);
                mma16816h(acc_o[2 * tp + 1], ph, &vh[2]);
            }
        }
    }

    float inv0 = 1.0f / l_run[0], inv1 = 1.0f / l_run[1];
#pragma unroll
    for (int nt = 0; nt < 4; nt++) {
        unsigned hi, lo;
        split2(acc_o[nt][0] * inv0, acc_o[nt][1] * inv0, hi, lo);
        size_t idx0 = (size_t)(b * N_ + iw + r) * CP + h * 16 + nt * 4 + c;
        g_att_hi[idx0] = hi; g_att_lo[idx0] = lo;
        split2(acc_o[nt][2] * inv1, acc_o[nt][3] * inv1, hi, lo);
        size_t idx1 = (size_t)(b * N_ + iw + r + 8) * CP + h * 16 + nt * 4 + c;
        g_att_hi[idx1] = hi; g_att_lo[idx1] = lo;
    }
}

// ---------------------------------------------------------------------------
extern "C" void kernel_launch(void* const* d_in, const int* in_sizes, int n_in,
                              void* d_out, int out_size) {
    const float* x     = (const float*)d_in[0];
    const float* W_qkv = (const float*)d_in[1];
    const float* W_prj = (const float*)d_in[2];
    const float* b_prj = (const float*)d_in[3];
    float* out = (float*)d_out;
    (void)in_sizes; (void)n_in; (void)out_size;

    static int attr_set = 0;
    if (!attr_set) {
        cudaFuncSetAttribute(gemm_bf16<0>, cudaFuncAttributeMaxDynamicSharedMemorySize,
                             GSMEM_TOTAL);
        cudaFuncSetAttribute(gemm_bf16<1>, cudaFuncAttributeMaxDynamicSharedMemorySize,
                             GSMEM_TOTAL);
        attr_set = 1;
    }

    dim3 gt(C_ / 32, N_ / 32, B_);           // 12 x 32 x 8
    split_x<<<gt, 256>>>(x);

    split_w<<<(O3 * CP + C_ * CP + 255) / 256, 256>>>(W_qkv, W_prj);

    dim3 g1(O3 / 128, N_ / 128, B_);         // 9 x 8 x 8
    gemm_bf16<0><<<g1, 512, GSMEM_TOTAL>>>(nullptr, nullptr);

    dim3 g2(N_ / 128, B_ * NH);              // 8 x 96
    attn_bf16<<<g2, 256>>>();

    dim3 g3(C_ / 128, N_ / 128, B_);         // 3 x 8 x 8
    gemm_bf16<1><<<g3, 512, GSMEM_TOTAL>>>(b_prj, out);
}

// round 10
// speedup vs baseline: 4.4281x; 1.3145x over previous
#include <cuda_runtime.h>
#include <cuda_bf16.h>
#include <math.h>

#define B_    8
#define NH    12
#define N_    1024
#define C_    384
#define CP    192       // C/2 (16-bit pairs per row)
#define O3    1152
#define O3P   576       // O3/2
#define QSC   (0.17677669529663687f * 1.4426950408889634f)   // SCALE*log2(e)

// ---------------- scratch (fp16x2 packed as u32) ----------------
// qkv cols [0,384): Q fp16 hi/lo (pre-scaled by QSC); [384,768): K fp16 hi;
// [768,1152): V fp16 hi.
static __device__ unsigned g_xT_hi[B_ * N_ * CP];
static __device__ unsigned g_xT_lo[B_ * N_ * CP];
static __device__ unsigned g_wq_hi[O3 * CP];
static __device__ unsigned g_wp_hi[C_ * CP];
static __device__ unsigned g_qkv_hi[B_ * N_ * O3P];
static __device__ unsigned g_qkv_lo[B_ * N_ * O3P];
static __device__ unsigned g_att_hi[B_ * N_ * CP];
static __device__ unsigned g_att_lo[B_ * N_ * CP];

__device__ __forceinline__ unsigned pack2h(float f0, float f1) {
    unsigned h;
    asm("cvt.rn.f16x2.f32 %0, %1, %2;" : "=r"(h) : "f"(f1), "f"(f0));
    return h;
}

// fp16 split: hi = rn16(f), lo = rn16(f - hi)
__device__ __forceinline__ void split2h(float f0, float f1, unsigned& hi, unsigned& lo) {
    unsigned h;
    asm("cvt.rn.f16x2.f32 %0, %1, %2;" : "=r"(h) : "f"(f1), "f"(f0));
    float h0, h1;
    asm("{.reg .f16 a,b;\n mov.b32 {a,b}, %2;\n cvt.f32.f16 %0, a;\n cvt.f32.f16 %1, b;}"
        : "=f"(h0), "=f"(h1) : "r"(h));
    hi = h;
    lo = pack2h(f0 - h0, f1 - h1);
}

__device__ __forceinline__ void mma16816h(float* d, const unsigned* a, const unsigned* b) {
    asm volatile(
        "mma.sync.aligned.m16n8k16.row.col.f32.f16.f16.f32 "
        "{%0,%1,%2,%3}, {%4,%5,%6,%7}, {%8,%9}, {%0,%1,%2,%3};"
        : "+f"(d[0]), "+f"(d[1]), "+f"(d[2]), "+f"(d[3])
        : "r"(a[0]), "r"(a[1]), "r"(a[2]), "r"(a[3]), "r"(b[0]), "r"(b[1]));
}

__device__ __forceinline__ float ex2(float x) {
    float y; asm("ex2.approx.ftz.f32 %0, %1;" : "=f"(y) : "f"(x)); return y;
}

__device__ __forceinline__ unsigned smem_u32p(const void* p) {
    return (unsigned)__cvta_generic_to_shared(p);
}

__device__ __forceinline__ void ldsm_x4(unsigned& r0, unsigned& r1,
                                        unsigned& r2, unsigned& r3, unsigned addr) {
    asm volatile("ldmatrix.sync.aligned.m8n8.x4.shared.b16 {%0,%1,%2,%3}, [%4];"
                 : "=r"(r0), "=r"(r1), "=r"(r2), "=r"(r3) : "r"(addr));
}

__device__ __forceinline__ void ldsm_x4_t(unsigned& r0, unsigned& r1,
                                          unsigned& r2, unsigned& r3, unsigned addr) {
    asm volatile("ldmatrix.sync.aligned.m8n8.x4.trans.shared.b16 {%0,%1,%2,%3}, [%4];"
                 : "=r"(r0), "=r"(r1), "=r"(r2), "=r"(r3) : "r"(addr));
}

__device__ __forceinline__ void cp16(unsigned dst, const void* src) {
    asm volatile("cp.async.cg.shared.global [%0], [%1], 16;" :: "r"(dst), "l"(src));
}
__device__ __forceinline__ void cp_commit() {
    asm volatile("cp.async.commit_group;" ::: "memory");
}
__device__ __forceinline__ void cp_wait0() {
    asm volatile("cp.async.wait_group 0;" ::: "memory");
}

// ---------------- pre-kernel 1: transpose + fp16-split x -> xT ------------
__global__ __launch_bounds__(256) void split_x(const float* __restrict__ x) {
    __shared__ float t[32][33];
    const int k0 = blockIdx.x * 32, m0 = blockIdx.y * 32, b = blockIdx.z;
    const int tx = threadIdx.x & 31, ty = threadIdx.x >> 5;
    const float* xb = x + ((size_t)b * C_ + k0) * N_ + m0;
#pragma unroll
    for (int q = 0; q < 4; q++) t[ty + q * 8][tx] = xb[(size_t)(ty + q * 8) * N_ + tx];
    __syncthreads();
    for (int it = threadIdx.x; it < 512; it += 256) {
        int mp = it >> 4, kp = it & 15;
        unsigned hi, lo;
        split2h(t[kp * 2][mp], t[kp * 2 + 1][mp], hi, lo);
        size_t idx = ((size_t)b * N_ + m0 + mp) * CP + (k0 >> 1) + kp;
        g_xT_hi[idx] = hi; g_xT_lo[idx] = lo;
    }
}

// ---------------- pre-kernel 2: weights -> fp16 hi only ----------------
__global__ __launch_bounds__(256) void split_w(const float* __restrict__ wq,
                                               const float* __restrict__ wp) {
    const int NQ = O3 * CP, NP = C_ * CP;
    int i = blockIdx.x * 256 + threadIdx.x;
    if (i < NQ) {
        float2 f = *(const float2*)(wq + 2 * (size_t)i);
        g_wq_hi[i] = pack2h(f.x, f.y);
    } else if (i < NQ + NP) {
        int j = i - NQ;
        float2 f = *(const float2*)(wp + 2 * (size_t)j);
        g_wp_hi[j] = pack2h(f.x, f.y);
    }
}

// ---------------- GEMM: 128m x 128n, 512 threads, fp16 2-term -------------
// C[m][n] = sum_k A[m][k]*B[n][k]; A = hi+lo, B = hi only.
// dynamic smem: Ah[2]@0, Al[2]@20480, Bh[2]@40960  (10240B per buffer)
#define GSMEM_TOTAL 61440
template <int EPI>
__global__ __launch_bounds__(512) void gemm_f16(const float* __restrict__ bias,
                                                float* __restrict__ out) {
    extern __shared__ unsigned gsm[];
    const unsigned smb = smem_u32p(gsm);

    const unsigned* Agh = EPI ? g_att_hi : g_xT_hi;
    const unsigned* Agl = EPI ? g_att_lo : g_xT_lo;
    const unsigned* Bgh = EPI ? g_wp_hi  : g_wq_hi;

    const int b = blockIdx.z;
    const int m0 = blockIdx.y * 128, n0 = blockIdx.x * 128;
    const int tid = threadIdx.x, lane = tid & 31, wid = tid >> 5;
    const int wm = (wid >> 2) * 32, wn = (wid & 3) * 32;
    const int r = lane >> 2, c = lane & 3;

    float acc[2][4][4] = {};

    const int srow = tid >> 2, sq = tid & 3;
    const unsigned* agp = Agh + (size_t)(b * N_ + m0 + srow) * CP + sq * 4;
    const unsigned* agl = Agl + (size_t)(b * N_ + m0 + srow) * CP + sq * 4;
    const unsigned* bgp = Bgh + (size_t)(n0 + srow) * CP + sq * 4;
    const unsigned dst0 = smb + (srow * 20 + sq * 4) * 4;

#define GEMM_STAGE(kc, sel)                                             \
    do {                                                                \
        unsigned so = (sel) * 10240;                                    \
        cp16(dst0 + so,         agp + (kc) * 16);                       \
        cp16(dst0 + 20480 + so, agl + (kc) * 16);                       \
        cp16(dst0 + 40960 + so, bgp + (kc) * 16);                       \
    } while (0)

    const unsigned offA = ((wm + (lane & 15)) * 20 + (lane >> 4) * 4) * 4;
    const unsigned baseAh = smb + offA;
    const unsigned baseAl = smb + 20480 + offA;
    const unsigned offB = ((wn + (lane & 7) + ((lane >> 4) << 3)) * 20 +
                           ((lane >> 3) & 1) * 4) * 4;
    const unsigned baseBh = smb + 40960 + offB;

    GEMM_STAGE(0, 0);
    cp_commit();

    for (int kc = 0; kc < 12; kc++) {
        const int sel = kc & 1;
        cp_wait0();
        __syncthreads();
        if (kc < 11) { GEMM_STAGE(kc + 1, sel ^ 1); cp_commit(); }

        const unsigned so = sel * 10240;
#pragma unroll
        for (int ks = 0; ks < 2; ks++) {
            unsigned ah[2][4], al[2][4];
#pragma unroll
            for (int mt = 0; mt < 2; mt++) {
                ldsm_x4(ah[mt][0], ah[mt][1], ah[mt][2], ah[mt][3],
                        baseAh + so + mt * 1280 + ks * 32);
                ldsm_x4(al[mt][0], al[mt][1], al[mt][2], al[mt][3],
                        baseAl + so + mt * 1280 + ks * 32);
            }
#pragma unroll
            for (int tp = 0; tp < 2; tp++) {
                unsigned bh[4];
                ldsm_x4(bh[0], bh[1], bh[2], bh[3], baseBh + so + tp * 1280 + ks * 32);
#pragma unroll
                for (int mt = 0; mt < 2; mt++) {
                    mma16816h(acc[mt][2 * tp],     ah[mt], &bh[0]);
                    mma16816h(acc[mt][2 * tp],     al[mt], &bh[0]);
                    mma16816h(acc[mt][2 * tp + 1], ah[mt], &bh[2]);
                    mma16816h(acc[mt][2 * tp + 1], al[mt], &bh[2]);
                }
            }
        }
    }

    if (EPI == 0) {
        // n0 is 128-aligned; boundaries 384/768 are 128-multiples
        const float qs = (n0 < 384) ? QSC : 1.0f;
        const bool needLo = (n0 < 384);      // only Q uses its lo part
#pragma unroll
        for (int mt = 0; mt < 2; mt++)
#pragma unroll
            for (int nt = 0; nt < 4; nt++) {
                int m = m0 + wm + mt * 16 + r;
                int colp = (n0 >> 1) + (wn >> 1) + nt * 4 + c;
                float a0 = acc[mt][nt][0] * qs, a1 = acc[mt][nt][1] * qs;
                float a2 = acc[mt][nt][2] * qs, a3 = acc[mt][nt][3] * qs;
                unsigned hi, lo;
                split2h(a0, a1, hi, lo);
                g_qkv_hi[(size_t)(b * N_ + m) * O3P + colp] = hi;
                if (needLo) g_qkv_lo[(size_t)(b * N_ + m) * O3P + colp] = lo;
                split2h(a2, a3, hi, lo);
                g_qkv_hi[(size_t)(b * N_ + m + 8) * O3P + colp] = hi;
                if (needLo) g_qkv_lo[(size_t)(b * N_ + m + 8) * O3P + colp] = lo;
            }
    } else {
#pragma unroll
        for (int mt = 0; mt < 2; mt++)
#pragma unroll
            for (int nt = 0; nt < 4; nt++)
#pragma unroll
                for (int q = 0; q < 4; q++) {
                    int o = n0 + wn + nt * 8 + 2 * c + (q & 1);
                    int m = m0 + wm + mt * 16 + r + ((q >> 1) * 8);
                    out[((size_t)b * C_ + o) * N_ + m] = acc[mt][nt][q] + bias[o];
                }
    }
}

// ---------------- flash attention ----------------
// Q fp16 hi/lo (pre-scaled, log2 domain), K fp16 hi, P fp16, V fp16 hi.
__global__ __launch_bounds__(256) void attn_f16() {
    __shared__ unsigned Ks_h[2][1280];   // [j=64][20] fp16 pairs
    __shared__ unsigned Vs_h[2][1280];   // [j=64][20] fp16 pairs

    const int tid = threadIdx.x, lane = tid & 31, wid = tid >> 5;
    const int bh = blockIdx.y, b = bh / NH, h = bh % NH;
    const int i0 = blockIdx.x * 128;
    const int iw = i0 + wid * 16;
    const int r = lane >> 2, c = lane & 3;

    unsigned qh[2][4], ql[2][4];
    {
        const unsigned* qb_h = g_qkv_hi + (size_t)(b * N_ + iw) * O3P + h * 16;
        const unsigned* qb_l = g_qkv_lo + (size_t)(b * N_ + iw) * O3P + h * 16;
#pragma unroll
        for (int ks = 0; ks < 2; ks++) {
            qh[ks][0] = qb_h[(size_t)r * O3P + ks * 8 + c];
            qh[ks][1] = qb_h[(size_t)(r + 8) * O3P + ks * 8 + c];
            qh[ks][2] = qb_h[(size_t)r * O3P + ks * 8 + 4 + c];
            qh[ks][3] = qb_h[(size_t)(r + 8) * O3P + ks * 8 + 4 + c];
            ql[ks][0] = qb_l[(size_t)r * O3P + ks * 8 + c];
            ql[ks][1] = qb_l[(size_t)(r + 8) * O3P + ks * 8 + c];
            ql[ks][2] = qb_l[(size_t)r * O3P + ks * 8 + 4 + c];
            ql[ks][3] = qb_l[(size_t)(r + 8) * O3P + ks * 8 + 4 + c];
        }
    }

    const int srow = tid >> 2, sq = tid & 3;
    const size_t srcK = (size_t)(b * N_ + srow) * O3P + 192 + h * 16 + sq * 4;
    const size_t srcV = (size_t)(b * N_ + srow) * O3P + 384 + h * 16 + sq * 4;
    const unsigned dK = smem_u32p(&Ks_h[0][srow * 20 + sq * 4]);
    const unsigned dV = smem_u32p(&Vs_h[0][srow * 20 + sq * 4]);

#define ATTN_STAGE(jt, sel)                                            \
    do {                                                               \
        size_t ro = (size_t)(jt) * 64 * O3P;                           \
        unsigned so = (sel) * 5120;                                    \
        cp16(dK + so, g_qkv_hi + srcK + ro);                           \
        cp16(dV + so, g_qkv_hi + srcV + ro);                           \
    } while (0)

    const unsigned offK = (((lane & 7) + ((lane >> 4) << 3)) * 20 +
                           ((lane >> 3) & 1) * 4) * 4;
    const unsigned baseKh = smem_u32p(Ks_h) + offK;
    const unsigned offV = (((lane >> 3) & 1) * 8 + (lane & 7)) * 80 +
                          (lane >> 4) * 16;
    const unsigned baseVh = smem_u32p(Vs_h) + offV;

    float m_run[2] = {-1e30f, -1e30f}, l_run[2] = {0.f, 0.f};
    float acc_o[4][4] = {};

    ATTN_STAGE(0, 0);
    cp_commit();

    for (int jt = 0; jt < 16; jt++) {
        const int sel = jt & 1;
        cp_wait0();
        __syncthreads();
        if (jt < 15) { ATTN_STAGE(jt + 1, sel ^ 1); cp_commit(); }

        const unsigned so = sel * 5120;

        float s[8][4] = {};
#pragma unroll
        for (int ks = 0; ks < 2; ks++)
#pragma unroll
            for (int tp = 0; tp < 4; tp++) {
                unsigned kh[4];
                ldsm_x4(kh[0], kh[1], kh[2], kh[3], baseKh + so + tp * 1280 + ks * 32);
                mma16816h(s[2 * tp],     qh[ks], &kh[0]);
                mma16816h(s[2 * tp],     ql[ks], &kh[0]);
                mma16816h(s[2 * tp + 1], qh[ks], &kh[2]);
                mma16816h(s[2 * tp + 1], ql[ks], &kh[2]);
            }

        float mx0 = m_run[0], mx1 = m_run[1];
#pragma unroll
        for (int nt = 0; nt < 8; nt++) {
            mx0 = fmaxf(mx0, fmaxf(s[nt][0], s[nt][1]));
            mx1 = fmaxf(mx1, fmaxf(s[nt][2], s[nt][3]));
        }
        mx0 = fmaxf(mx0, __shfl_xor_sync(0xffffffffu, mx0, 1));
        mx0 = fmaxf(mx0, __shfl_xor_sync(0xffffffffu, mx0, 2));
        mx1 = fmaxf(mx1, __shfl_xor_sync(0xffffffffu, mx1, 1));
        mx1 = fmaxf(mx1, __shfl_xor_sync(0xffffffffu, mx1, 2));
        float corr0 = ex2(m_run[0] - mx0);
        float corr1 = ex2(m_run[1] - mx1);
        float rs0 = 0.f, rs1 = 0.f;
#pragma unroll
        for (int nt = 0; nt < 8; nt++) {
            s[nt][0] = ex2(s[nt][0] - mx0);
            s[nt][1] = ex2(s[nt][1] - mx0);
            s[nt][2] = ex2(s[nt][2] - mx1);
            s[nt][3] = ex2(s[nt][3] - mx1);
            rs0 += s[nt][0] + s[nt][1];
            rs1 += s[nt][2] + s[nt][3];
        }
        rs0 += __shfl_xor_sync(0xffffffffu, rs0, 1);
        rs0 += __shfl_xor_sync(0xffffffffu, rs0, 2);
        rs1 += __shfl_xor_sync(0xffffffffu, rs1, 1);
        rs1 += __shfl_xor_sync(0xffffffffu, rs1, 2);
        l_run[0] = l_run[0] * corr0 + rs0;
        l_run[1] = l_run[1] * corr1 + rs1;
        m_run[0] = mx0; m_run[1] = mx1;
#pragma unroll
        for (int nt = 0; nt < 4; nt++) {
            acc_o[nt][0] *= corr0; acc_o[nt][1] *= corr0;
            acc_o[nt][2] *= corr1; acc_o[nt][3] *= corr1;
        }

#pragma unroll
        for (int kk = 0; kk < 4; kk++) {
            unsigned ph[4];
            ph[0] = pack2h(s[2 * kk][0], s[2 * kk][1]);
            ph[1] = pack2h(s[2 * kk][2], s[2 * kk][3]);
            ph[2] = pack2h(s[2 * kk + 1][0], s[2 * kk + 1][1]);
            ph[3] = pack2h(s[2 * kk + 1][2], s[2 * kk + 1][3]);
#pragma unroll
            for (int tp = 0; tp < 2; tp++) {
                unsigned vh[4];
                ldsm_x4_t(vh[0], vh[1], vh[2], vh[3],
                          baseVh + so + kk * 1280 + tp * 32);
                mma16816h(acc_o[2 * tp],     ph, &vh[0]);
                mma16816h(acc_o[2 * tp + 1], ph, &vh[2]);
            }
        }
    }

    float inv0 = 1.0f / l_run[0], inv1 = 1.0f / l_run[1];
#pragma unroll
    for (int nt = 0; nt < 4; nt++) {
        unsigned hi, lo;
        split2h(acc_o[nt][0] * inv0, acc_o[nt][1] * inv0, hi, lo);
        size_t idx0 = (size_t)(b * N_ + iw + r) * CP + h * 16 + nt * 4 + c;
        g_att_hi[idx0] = hi; g_att_lo[idx0] = lo;
        split2h(acc_o[nt][2] * inv1, acc_o[nt][3] * inv1, hi, lo);
        size_t idx1 = (size_t)(b * N_ + iw + r + 8) * CP + h * 16 + nt * 4 + c;
        g_att_hi[idx1] = hi; g_att_lo[idx1] = lo;
    }
}

// ---------------------------------------------------------------------------
extern "C" void kernel_launch(void* const* d_in, const int* in_sizes, int n_in,
                              void* d_out, int out_size) {
    const float* x     = (const float*)d_in[0];
    const float* W_qkv = (const float*)d_in[1];
    const float* W_prj = (const float*)d_in[2];
    const float* b_prj = (const float*)d_in[3];
    float* out = (float*)d_out;
    (void)in_sizes; (void)n_in; (void)out_size;

    static int attr_set = 0;
    if (!attr_set) {
        cudaFuncSetAttribute(gemm_f16<0>, cudaFuncAttributeMaxDynamicSharedMemorySize,
                             GSMEM_TOTAL);
        cudaFuncSetAttribute(gemm_f16<1>, cudaFuncAttributeMaxDynamicSharedMemorySize,
                             GSMEM_TOTAL);
        attr_set = 1;
    }

    dim3 gt(C_ / 32, N_ / 32, B_);           // 12 x 32 x 8
    split_x<<<gt, 256>>>(x);

    split_w<<<(O3 * CP + C_ * CP + 255) / 256, 256>>>(W_qkv, W_prj);

    dim3 g1(O3 / 128, N_ / 128, B_);         // 9 x 8 x 8
    gemm_f16<0><<<g1, 512, GSMEM_TOTAL>>>(nullptr, nullptr);

    dim3 g2(N_ / 128, B_ * NH);              // 8 x 96
    attn_f16<<<g2, 256>>>();

    dim3 g3(C_ / 128, N_ / 128, B_);         // 3 x 8 x 8
    gemm_f16<1><<<g3, 512, GSMEM_TOTAL>>>(b_prj, out);
}

// round 13
// speedup vs baseline: 4.4652x; 1.0084x over previous
#include <cuda_runtime.h>
#include <cuda_bf16.h>
#include <math.h>

#define B_    8
#define NH    12
#define N_    1024
#define C_    384
#define CP    192       // C/2 (16-bit pairs per row)
#define O3    1152
#define O3P   576       // O3/2
#define QSC   (0.17677669529663687f * 1.4426950408889634f)   // SCALE*log2(e)

// ---------------- scratch (fp16x2 packed as u32) ----------------
// qkv cols [0,384): Q fp16 hi/lo (pre-scaled by QSC); [384,768): K fp16 hi;
// [768,1152): V fp16 hi.
static __device__ unsigned g_xT_hi[B_ * N_ * CP];
static __device__ unsigned g_xT_lo[B_ * N_ * CP];
static __device__ unsigned g_wq_hi[O3 * CP];
static __device__ unsigned g_wp_hi[C_ * CP];
static __device__ unsigned g_qkv_hi[B_ * N_ * O3P];
static __device__ unsigned g_qkv_lo[B_ * N_ * O3P];
static __device__ unsigned g_att_hi[B_ * N_ * CP];
static __device__ unsigned g_att_lo[B_ * N_ * CP];

__device__ __forceinline__ unsigned pack2h(float f0, float f1) {
    unsigned h;
    asm("cvt.rn.f16x2.f32 %0, %1, %2;" : "=r"(h) : "f"(f1), "f"(f0));
    return h;
}

__device__ __forceinline__ unsigned ex2h2(unsigned x) {
    unsigned y;
    asm("ex2.approx.f16x2 %0, %1;" : "=r"(y) : "r"(x));
    return y;
}

// fp16 split: hi = rn16(f), lo = rn16(f - hi)
__device__ __forceinline__ void split2h(float f0, float f1, unsigned& hi, unsigned& lo) {
    unsigned h;
    asm("cvt.rn.f16x2.f32 %0, %1, %2;" : "=r"(h) : "f"(f1), "f"(f0));
    float h0, h1;
    asm("{.reg .f16 a,b;\n mov.b32 {a,b}, %2;\n cvt.f32.f16 %0, a;\n cvt.f32.f16 %1, b;}"
        : "=f"(h0), "=f"(h1) : "r"(h));
    hi = h;
    lo = pack2h(f0 - h0, f1 - h1);
}

__device__ __forceinline__ void mma16816h(float* d, const unsigned* a, const unsigned* b) {
    asm volatile(
        "mma.sync.aligned.m16n8k16.row.col.f32.f16.f16.f32 "
        "{%0,%1,%2,%3}, {%4,%5,%6,%7}, {%8,%9}, {%0,%1,%2,%3};"
        : "+f"(d[0]), "+f"(d[1]), "+f"(d[2]), "+f"(d[3])
        : "r"(a[0]), "r"(a[1]), "r"(a[2]), "r"(a[3]), "r"(b[0]), "r"(b[1]));
}

__device__ __forceinline__ float ex2(float x) {
    float y; asm("ex2.approx.ftz.f32 %0, %1;" : "=f"(y) : "f"(x)); return y;
}

__device__ __forceinline__ unsigned smem_u32p(const void* p) {
    return (unsigned)__cvta_generic_to_shared(p);
}

__device__ __forceinline__ void ldsm_x4(unsigned& r0, unsigned& r1,
                                        unsigned& r2, unsigned& r3, unsigned addr) {
    asm volatile("ldmatrix.sync.aligned.m8n8.x4.shared.b16 {%0,%1,%2,%3}, [%4];"
                 : "=r"(r0), "=r"(r1), "=r"(r2), "=r"(r3) : "r"(addr));
}

__device__ __forceinline__ void ldsm_x4_t(unsigned& r0, unsigned& r1,
                                          unsigned& r2, unsigned& r3, unsigned addr) {
    asm volatile("ldmatrix.sync.aligned.m8n8.x4.trans.shared.b16 {%0,%1,%2,%3}, [%4];"
                 : "=r"(r0), "=r"(r1), "=r"(r2), "=r"(r3) : "r"(addr));
}

__device__ __forceinline__ void cp16(unsigned dst, const void* src) {
    asm volatile("cp.async.cg.shared.global [%0], [%1], 16;" :: "r"(dst), "l"(src));
}
__device__ __forceinline__ void cp_commit() {
    asm volatile("cp.async.commit_group;" ::: "memory");
}
__device__ __forceinline__ void cp_wait0() {
    asm volatile("cp.async.wait_group 0;" ::: "memory");
}

// ---------------- pre-kernel 1: transpose + fp16-split x -> xT ------------
__global__ __launch_bounds__(256) void split_x(const float* __restrict__ x) {
    __shared__ float t[32][33];
    const int k0 = blockIdx.x * 32, m0 = blockIdx.y * 32, b = blockIdx.z;
    const int tx = threadIdx.x & 31, ty = threadIdx.x >> 5;
    const float* xb = x + ((size_t)b * C_ + k0) * N_ + m0;
#pragma unroll
    for (int q = 0; q < 4; q++) t[ty + q * 8][tx] = xb[(size_t)(ty + q * 8) * N_ + tx];
    __syncthreads();
    for (int it = threadIdx.x; it < 512; it += 256) {
        int mp = it >> 4, kp = it & 15;
        unsigned hi, lo;
        split2h(t[kp * 2][mp], t[kp * 2 + 1][mp], hi, lo);
        size_t idx = ((size_t)b * N_ + m0 + mp) * CP + (k0 >> 1) + kp;
        g_xT_hi[idx] = hi; g_xT_lo[idx] = lo;
    }
}

// ---------------- pre-kernel 2: weights -> fp16 hi only ----------------
__global__ __launch_bounds__(256) void split_w(const float* __restrict__ wq,
                                               const float* __restrict__ wp) {
    const int NQ = O3 * CP, NP = C_ * CP;
    int i = blockIdx.x * 256 + threadIdx.x;
    if (i < NQ) {
        float2 f = *(const float2*)(wq + 2 * (size_t)i);
        g_wq_hi[i] = pack2h(f.x, f.y);
    } else if (i < NQ + NP) {
        int j = i - NQ;
        float2 f = *(const float2*)(wp + 2 * (size_t)j);
        g_wp_hi[j] = pack2h(f.x, f.y);
    }
}

// ---------------- GEMM: 128m x 128n, 512 threads, fp16 2-term -------------
#define GSMEM_TOTAL 61440
template <int EPI>
__global__ __launch_bounds__(512) void gemm_f16(const float* __restrict__ bias,
                                                float* __restrict__ out) {
    extern __shared__ unsigned gsm[];
    const unsigned smb = smem_u32p(gsm);

    const unsigned* Agh = EPI ? g_att_hi : g_xT_hi;
    const unsigned* Agl = EPI ? g_att_lo : g_xT_lo;
    const unsigned* Bgh = EPI ? g_wp_hi  : g_wq_hi;

    const int b = blockIdx.z;
    const int m0 = blockIdx.y * 128, n0 = blockIdx.x * 128;
    const int tid = threadIdx.x, lane = tid & 31, wid = tid >> 5;
    const int wm = (wid >> 2) * 32, wn = (wid & 3) * 32;
    const int r = lane >> 2, c = lane & 3;

    float acc[2][4][4] = {};

    const int srow = tid >> 2, sq = tid & 3;
    const unsigned* agp = Agh + (size_t)(b * N_ + m0 + srow) * CP + sq * 4;
    const unsigned* agl = Agl + (size_t)(b * N_ + m0 + srow) * CP + sq * 4;
    const unsigned* bgp = Bgh + (size_t)(n0 + srow) * CP + sq * 4;
    const unsigned dst0 = smb + (srow * 20 + sq * 4) * 4;

#define GEMM_STAGE(kc, sel)                                             \
    do {                                                                \
        unsigned so = (sel) * 10240;                                    \
        cp16(dst0 + so,         agp + (kc) * 16);                       \
        cp16(dst0 + 20480 + so, agl + (kc) * 16);                       \
        cp16(dst0 + 40960 + so, bgp + (kc) * 16);                       \
    } while (0)

    const unsigned offA = ((wm + (lane & 15)) * 20 + (lane >> 4) * 4) * 4;
    const unsigned baseAh = smb + offA;
    const unsigned baseAl = smb + 20480 + offA;
    const unsigned offB = ((wn + (lane & 7) + ((lane >> 4) << 3)) * 20 +
                           ((lane >> 3) & 1) * 4) * 4;
    const unsigned baseBh = smb + 40960 + offB;

    GEMM_STAGE(0, 0);
    cp_commit();

    for (int kc = 0; kc < 12; kc++) {
        const int sel = kc & 1;
        cp_wait0();
        __syncthreads();
        if (kc < 11) { GEMM_STAGE(kc + 1, sel ^ 1); cp_commit(); }

        const unsigned so = sel * 10240;
#pragma unroll
        for (int ks = 0; ks < 2; ks++) {
            unsigned ah[2][4], al[2][4];
#pragma unroll
            for (int mt = 0; mt < 2; mt++) {
                ldsm_x4(ah[mt][0], ah[mt][1], ah[mt][2], ah[mt][3],
                        baseAh + so + mt * 1280 + ks * 32);
                ldsm_x4(al[mt][0], al[mt][1], al[mt][2], al[mt][3],
                        baseAl + so + mt * 1280 + ks * 32);
            }
#pragma unroll
            for (int tp = 0; tp < 2; tp++) {
                unsigned bh[4];
                ldsm_x4(bh[0], bh[1], bh[2], bh[3], baseBh + so + tp * 1280 + ks * 32);
#pragma unroll
                for (int mt = 0; mt < 2; mt++) {
                    mma16816h(acc[mt][2 * tp],     ah[mt], &bh[0]);
                    mma16816h(acc[mt][2 * tp],     al[mt], &bh[0]);
                    mma16816h(acc[mt][2 * tp + 1], ah[mt], &bh[2]);
                    mma16816h(acc[mt][2 * tp + 1], al[mt], &bh[2]);
                }
            }
        }
    }

    if (EPI == 0) {
        const float qs = (n0 < 384) ? QSC : 1.0f;
        const bool needLo = (n0 < 384);      // only Q uses its lo part
#pragma unroll
        for (int mt = 0; mt < 2; mt++)
#pragma unroll
            for (int nt = 0; nt < 4; nt++) {
                int m = m0 + wm + mt * 16 + r;
                int colp = (n0 >> 1) + (wn >> 1) + nt * 4 + c;
                float a0 = acc[mt][nt][0] * qs, a1 = acc[mt][nt][1] * qs;
                float a2 = acc[mt][nt][2] * qs, a3 = acc[mt][nt][3] * qs;
                unsigned hi, lo;
                split2h(a0, a1, hi, lo);
                g_qkv_hi[(size_t)(b * N_ + m) * O3P + colp] = hi;
                if (needLo) g_qkv_lo[(size_t)(b * N_ + m) * O3P + colp] = lo;
                split2h(a2, a3, hi, lo);
                g_qkv_hi[(size_t)(b * N_ + m + 8) * O3P + colp] = hi;
                if (needLo) g_qkv_lo[(size_t)(b * N_ + m + 8) * O3P + colp] = lo;
            }
    } else {
#pragma unroll
        for (int mt = 0; mt < 2; mt++)
#pragma unroll
            for (int nt = 0; nt < 4; nt++)
#pragma unroll
                for (int q = 0; q < 4; q++) {
                    int o = n0 + wn + nt * 8 + 2 * c + (q & 1);
                    int m = m0 + wm + mt * 16 + r + ((q >> 1) * 8);
                    out[((size_t)b * C_ + o) * N_ + m] = acc[mt][nt][q] + bias[o];
                }
    }
}

// ---------------- flash attention ----------------
// Q fp16 hi/lo (pre-scaled, log2 domain), K fp16 hi, P fp16 (ex2.f16x2),
// V fp16 hi; row-sum l computed by an extra MMA against an all-ones B.
__global__ __launch_bounds__(256, 3) void attn_f16() {
    __shared__ unsigned Ks_h[2][1280];   // [j=64][20] fp16 pairs
    __shared__ unsigned Vs_h[2][1280];   // [j=64][20] fp16 pairs

    const int tid = threadIdx.x, lane = tid & 31, wid = tid >> 5;
    const int bh = blockIdx.y, b = bh / NH, h = bh % NH;
    const int i0 = blockIdx.x * 128;
    const int iw = i0 + wid * 16;
    const int r = lane >> 2, c = lane & 3;

    unsigned qh[2][4], ql[2][4];
    {
        const unsigned* qb_h = g_qkv_hi + (size_t)(b * N_ + iw) * O3P + h * 16;
        const unsigned* qb_l = g_qkv_lo + (size_t)(b * N_ + iw) * O3P + h * 16;
#pragma unroll
        for (int ks = 0; ks < 2; ks++) {
            qh[ks][0] = qb_h[(size_t)r * O3P + ks * 8 + c];
            qh[ks][1] = qb_h[(size_t)(r + 8) * O3P + ks * 8 + c];
            qh[ks][2] = qb_h[(size_t)r * O3P + ks * 8 + 4 + c];
            qh[ks][3] = qb_h[(size_t)(r + 8) * O3P + ks * 8 + 4 + c];
            ql[ks][0] = qb_l[(size_t)r * O3P + ks * 8 + c];
            ql[ks][1] = qb_l[(size_t)(r + 8) * O3P + ks * 8 + c];
            ql[ks][2] = qb_l[(size_t)r * O3P + ks * 8 + 4 + c];
            ql[ks][3] = qb_l[(size_t)(r + 8) * O3P + ks * 8 + 4 + c];
        }
    }

    const int srow = tid >> 2, sq = tid & 3;
    const size_t srcK = (size_t)(b * N_ + srow) * O3P + 192 + h * 16 + sq * 4;
    const size_t srcV = (size_t)(b * N_ + srow) * O3P + 384 + h * 16 + sq * 4;
    const unsigned dK = smem_u32p(&Ks_h[0][srow * 20 + sq * 4]);
    const unsigned dV = smem_u32p(&Vs_h[0][srow * 20 + sq * 4]);

#define ATTN_STAGE(jt, sel)                                            \
    do {                                                               \
        size_t ro = (size_t)(jt) * 64 * O3P;                           \
        unsigned so = (sel) * 5120;                                    \
        cp16(dK + so, g_qkv_hi + srcK + ro);                           \
        cp16(dV + so, g_qkv_hi + srcV + ro);                           \
    } while (0)

    const unsigned offK = (((lane & 7) + ((lane >> 4) << 3)) * 20 +
                           ((lane >> 3) & 1) * 4) * 4;
    const unsigned baseKh = smem_u32p(Ks_h) + offK;
    const unsigned offV = (((lane >> 3) & 1) * 8 + (lane & 7)) * 80 +
                          (lane >> 4) * 16;
    const unsigned baseVh = smem_u32p(Vs_h) + offV;

    float m_run[2] = {-1e30f, -1e30f}, l_run[2] = {0.f, 0.f};
    float acc_o[4][4] = {};
    const unsigned onesb[2] = {0x3C003C00u, 0x3C003C00u};

    ATTN_STAGE(0, 0);
    cp_commit();

    for (int jt = 0; jt < 16; jt++) {
        const int sel = jt & 1;
        cp_wait0();
        __syncthreads();
        if (jt < 15) { ATTN_STAGE(jt + 1, sel ^ 1); cp_commit(); }

        const unsigned so = sel * 5120;

        float s[8][4] = {};
#pragma unroll
        for (int ks = 0; ks < 2; ks++)
#pragma unroll
            for (int tp = 0; tp < 4; tp++) {
                unsigned kh[4];
                ldsm_x4(kh[0], kh[1], kh[2], kh[3], baseKh + so + tp * 1280 + ks * 32);
                mma16816h(s[2 * tp],     qh[ks], &kh[0]);
                mma16816h(s[2 * tp],     ql[ks], &kh[0]);
                mma16816h(s[2 * tp + 1], qh[ks], &kh[2]);
                mma16816h(s[2 * tp + 1], ql[ks], &kh[2]);
            }

        // row max (fp32) across 4 lanes sharing each row
        float mx0 = m_run[0], mx1 = m_run[1];
#pragma unroll
        for (int nt = 0; nt < 8; nt++) {
            mx0 = fmaxf(mx0, fmaxf(s[nt][0], s[nt][1]));
            mx1 = fmaxf(mx1, fmaxf(s[nt][2], s[nt][3]));
        }
        mx0 = fmaxf(mx0, __shfl_xor_sync(0xffffffffu, mx0, 1));
        mx0 = fmaxf(mx0, __shfl_xor_sync(0xffffffffu, mx0, 2));
        mx1 = fmaxf(mx1, __shfl_xor_sync(0xffffffffu, mx1, 1));
        mx1 = fmaxf(mx1, __shfl_xor_sync(0xffffffffu, mx1, 2));
        float corr0 = ex2(m_run[0] - mx0);
        float corr1 = ex2(m_run[1] - mx1);
        m_run[0] = mx0; m_run[1] = mx1;
#pragma unroll
        for (int nt = 0; nt < 4; nt++) {
            acc_o[nt][0] *= corr0; acc_o[nt][1] *= corr0;
            acc_o[nt][2] *= corr1; acc_o[nt][3] *= corr1;
        }

        // l accumulator seeded with rescaled running sums; MMA-with-ones adds
        // this tile's row sums (exact fp32, replicated across the lane quad).
        float accl[4] = {l_run[0] * corr0, 0.f, l_run[1] * corr1, 0.f};

        // P = ex2(s - mx) computed directly in fp16x2; feeds PV + l-MMA
#pragma unroll
        for (int kk = 0; kk < 4; kk++) {
            unsigned ph[4];
            ph[0] = ex2h2(pack2h(s[2 * kk][0] - mx0,     s[2 * kk][1] - mx0));
            ph[1] = ex2h2(pack2h(s[2 * kk][2] - mx1,     s[2 * kk][3] - mx1));
            ph[2] = ex2h2(pack2h(s[2 * kk + 1][0] - mx0, s[2 * kk + 1][1] - mx0));
            ph[3] = ex2h2(pack2h(s[2 * kk + 1][2] - mx1, s[2 * kk + 1][3] - mx1));
            mma16816h(accl, ph, onesb);
#pragma unroll
            for (int tp = 0; tp < 2; tp++) {
                unsigned vh[4];
                ldsm_x4_t(vh[0], vh[1], vh[2], vh[3],
                          baseVh + so + kk * 1280 + tp * 32);
                mma16816h(acc_o[2 * tp],     ph, &vh[0]);
                mma16816h(acc_o[2 * tp + 1], ph, &vh[2]);
            }
        }
        l_run[0] = accl[0]; l_run[1] = accl[2];
    }

    float inv0 = 1.0f / l_run[0], inv1 = 1.0f / l_run[1];
#pragma unroll
    for (int nt = 0; nt < 4; nt++) {
        unsigned hi, lo;
        split2h(acc_o[nt][0] * inv0, acc_o[nt][1] * inv0, hi, lo);
        size_t idx0 = (size_t)(b * N_ + iw + r) * CP + h * 16 + nt * 4 + c;
        g_att_hi[idx0] = hi; g_att_lo[idx0] = lo;
        split2h(acc_o[nt][2] * inv1, acc_o[nt][3] * inv1, hi, lo);
        size_t idx1 = (size_t)(b * N_ + iw + r + 8) * CP + h * 16 + nt * 4 + c;
        g_att_hi[idx1] = hi; g_att_lo[idx1] = lo;
    }
}

// ---------------------------------------------------------------------------
extern "C" void kernel_launch(void* const* d_in, const int* in_sizes, int n_in,
                              void* d_out, int out_size) {
    const float* x     = (const float*)d_in[0];
    const float* W_qkv = (const float*)d_in[1];
    const float* W_prj = (const float*)d_in[2];
    const float* b_prj = (const float*)d_in[3];
    float* out = (float*)d_out;
    (void)in_sizes; (void)n_in; (void)out_size;

    static int attr_set = 0;
    if (!attr_set) {
        cudaFuncSetAttribute(gemm_f16<0>, cudaFuncAttributeMaxDynamicSharedMemorySize,
                             GSMEM_TOTAL);
        cudaFuncSetAttribute(gemm_f16<1>, cudaFuncAttributeMaxDynamicSharedMemorySize,
                             GSMEM_TOTAL);
        attr_set = 1;
    }

    dim3 gt(C_ / 32, N_ / 32, B_);           // 12 x 32 x 8
    split_x<<<gt, 256>>>(x);

    split_w<<<(O3 * CP + C_ * CP + 255) / 256, 256>>>(W_qkv, W_prj);

    dim3 g1(O3 / 128, N_ / 128, B_);         // 9 x 8 x 8
    gemm_f16<0><<<g1, 512, GSMEM_TOTAL>>>(nullptr, nullptr);

    dim3 g2(N_ / 128, B_ * NH);              // 8 x 96
    attn_f16<<<g2, 256>>>();

    dim3 g3(C_ / 128, N_ / 128, B_);         // 3 x 8 x 8
    gemm_f16<1><<<g3, 512, GSMEM_TOTAL>>>(b_prj, out);
}